// round 12
// baseline (speedup 1.0000x reference)
#include <cuda_runtime.h>
#include <math.h>

#define Nn 2048
#define Dd 256
#define Qq 16
#define Mm 64
#define MMs 4096
#define NPAIR 2080
#define NBLK 444
#define NUNITS 448
#define LOG2E 1.4426950408889634f
#define LN2f  0.6931471805599453f

// -------- scratch (device globals; zero at load, re-zeroed by GJ tail) -----
__device__ alignas(16) float g_psi2[MMs];
__device__ alignas(16) float g_A[Mm*Dd];
__device__ alignas(16) float g_G[MMs];
__device__ float  g_scal[8];          // [0]=KL sum, [1]=sum(y*y)
__device__ unsigned g_Gdone;
__device__ unsigned g_cnt;
__device__ volatile unsigned g_gen;

__device__ __forceinline__ float softplus_f(float x) {
    float ax = fabsf(x);
    return fmaxf(x, 0.0f) + log1pf(__expf(-ax));
}
__device__ __forceinline__ float ex2(float x) {
    float y; asm("ex2.approx.f32 %0, %1;" : "=f"(y) : "f"(x)); return y;
}
__device__ __forceinline__ float lg2(float x) {
    float y; asm("lg2.approx.f32 %0, %1;" : "=f"(y) : "f"(x)); return y;
}
// FMA-pipe exp2 (psi2 hot loop; avoids MUFU wall). |rel err| ~2.4e-6
__device__ __forceinline__ float exp2_fast(float x) {
    x = fmaxf(x, -125.0f);
    float r = rintf(x);
    float f = x - r;
    int   i = (int)r;
    float p =          1.3333558146e-3f;
    p = fmaf(p, f,     9.6181291076e-3f);
    p = fmaf(p, f,     5.5504108664e-2f);
    p = fmaf(p, f,     2.4022650696e-1f);
    p = fmaf(p, f,     6.9314718056e-1f);
    p = fmaf(p, f,     1.0f);
    return __int_as_float(__float_as_int(p) + (i << 23));
}

// ---- packed f32x2 helpers ----
__device__ __forceinline__ unsigned long long pk2(float lo, float hi) {
    unsigned long long r;
    asm("mov.b64 %0, {%1, %2};" : "=l"(r) : "f"(lo), "f"(hi));
    return r;
}
__device__ __forceinline__ void upk2(unsigned long long v, float& lo, float& hi) {
    asm("mov.b64 {%0, %1}, %2;" : "=f"(lo), "=f"(hi) : "l"(v));
}
__device__ __forceinline__ unsigned long long fma2(unsigned long long a,
                                                   unsigned long long b,
                                                   unsigned long long c) {
    unsigned long long d;
    asm("fma.rn.f32x2 %0, %1, %2, %3;" : "=l"(d) : "l"(a), "l"(b), "l"(c));
    return d;
}
__device__ __forceinline__ unsigned long long add2(unsigned long long a,
                                                   unsigned long long b) {
    unsigned long long d;
    asm("add.rn.f32x2 %0, %1, %2;" : "=l"(d) : "l"(a), "l"(b));
    return d;
}

__device__ __forceinline__ int tri_base(int i) { return i*Mm - ((i*(i-1)) >> 1); }
__device__ __forceinline__ void pair_ij(int p, int& io, int& jo) {
    int ii = (int)(0.5f*(129.0f - sqrtf(fmaf(-8.f, (float)p, 16641.f))));
    while (tri_base(ii+1) <= p) ii++;
    while (tri_base(ii)   >  p) ii--;
    io = ii;
    jo = p - tri_base(ii) + ii;
}

// grid-wide barrier (444 co-resident blocks at 3 CTA/SM)
__device__ __forceinline__ void grid_bar() {
    __threadfence();
    __syncthreads();
    if (threadIdx.x == 0) {
        unsigned gen = g_gen;
        if (atomicAdd(&g_cnt, 1u) == NBLK - 1u) {
            g_cnt = 0u;
            __threadfence();
            g_gen = gen + 1u;
        } else {
            while (g_gen == gen) __nanosleep(32);
        }
    }
    __syncthreads();
    __threadfence();
}

__global__ void __launch_bounds__(256, 3) fused(
        const float* __restrict__ y,    const float* __restrict__ qmu,
        const float* __restrict__ qls,  const float* __restrict__ z,
        const float* __restrict__ noise,const float* __restrict__ alpha,
        const float* __restrict__ varp, float* __restrict__ out) {
    __shared__ alignas(16) char SM[27648];
    const int bx = blockIdx.x, tid = threadIdx.x;

    // ===================== PHASE 1: 448 units over 444 blocks ================
    for (int u = bx; u < NUNITS; u += NBLK) {
        __syncthreads();   // smem reuse fence between units
        if (u < 320) {
            // ---- psi2 unit: pg=u>>6 → 512 pair-slots; 32 n rows ----
            float* zsh  = (float*)SM;              // 1024 f
            float* sal  = (float*)(SM + 4096);     // 16 f
            float* sR2f = (float*)(SM + 4224);     // 32 rows x 144B: u[16], wneg[16], a
            ((float4*)zsh)[tid] = ((const float4*)z)[tid];
            if (tid < Qq) sal[tid] = alpha[tid];
            __syncthreads();
            int pg = u >> 6, ny = u & 63;
            int n0 = ny * 32;
            if (tid < 32) {
                int n = n0 + tid;
                float lv2 = lg2(varp[0]);
                float prodD2 = 1.f, P = 0.f;
                float* rw = &sR2f[tid*36];
                #pragma unroll
                for (int q = 0; q < Qq; q++) {
                    float mu = qmu[n*Qq + q];
                    float x  = qls[n*Qq + q];
                    float e  = ex2(-LOG2E * fabsf(x));
                    float sg = fmaxf(x, 0.f) + LN2f * lg2(1.0f + e);
                    float al = sal[q];
                    float d2 = fmaf(2.0f*al, sg, 1.0f);
                    prodD2 *= d2;
                    float w2 = __fdividef(al, d2);
                    P += w2*mu*mu;
                    rw[q]      = LOG2E * 2.0f * w2 * mu;   // u'_q
                    rw[16 + q] = -LOG2E * w2;              // wneg'_q
                }
                rw[32] = 4.0f*lv2 - 0.5f*lg2(prodD2) - LOG2E * P;  // a'_n
            }
            int p0 = (pg*256 + tid)*2;
            int iA, jA, iB, jB;
            pair_ij(min(p0,   NPAIR-1), iA, jA);
            pair_ij(min(p0+1, NPAIR-1), iB, jB);
            unsigned long long zpA[8], zpB[8];
            float bA, bB;
            {
                float S = 0.f;
                #pragma unroll
                for (int k = 0; k < 4; k++) {
                    float4 zi = ((const float4*)(zsh + iA*Qq))[k];
                    float4 zj = ((const float4*)(zsh + jA*Qq))[k];
                    zpA[2*k]   = pk2(0.5f*(zi.x+zj.x), 0.5f*(zi.y+zj.y));
                    zpA[2*k+1] = pk2(0.5f*(zi.z+zj.z), 0.5f*(zi.w+zj.w));
                    float dx = zi.x-zj.x, dy = zi.y-zj.y, dz = zi.z-zj.z, dw = zi.w-zj.w;
                    S = fmaf(sal[4*k+0]*dx, dx, S); S = fmaf(sal[4*k+1]*dy, dy, S);
                    S = fmaf(sal[4*k+2]*dz, dz, S); S = fmaf(sal[4*k+3]*dw, dw, S);
                }
                bA = -0.25f * LOG2E * S;
            }
            {
                float S = 0.f;
                #pragma unroll
                for (int k = 0; k < 4; k++) {
                    float4 zi = ((const float4*)(zsh + iB*Qq))[k];
                    float4 zj = ((const float4*)(zsh + jB*Qq))[k];
                    zpB[2*k]   = pk2(0.5f*(zi.x+zj.x), 0.5f*(zi.y+zj.y));
                    zpB[2*k+1] = pk2(0.5f*(zi.z+zj.z), 0.5f*(zi.w+zj.w));
                    float dx = zi.x-zj.x, dy = zi.y-zj.y, dz = zi.z-zj.z, dw = zi.w-zj.w;
                    S = fmaf(sal[4*k+0]*dx, dx, S); S = fmaf(sal[4*k+1]*dy, dy, S);
                    S = fmaf(sal[4*k+2]*dz, dz, S); S = fmaf(sal[4*k+3]*dw, dw, S);
                }
                bB = -0.25f * LOG2E * S;
            }
            __syncthreads();
            float sumA = 0.f, sumB = 0.f;
            #pragma unroll 2
            for (int i = 0; i < 32; i++) {
                const char* rowp = (const char*)sR2f + i*144;
                const ulonglong2* up = (const ulonglong2*)rowp;        // u packed
                const ulonglong2* wp = (const ulonglong2*)(rowp + 64); // wneg packed
                float an = ((const float*)rowp)[32];
                unsigned long long a0 = 0, a1 = 0, b0 = 0, b1 = 0;
                #pragma unroll
                for (int j = 0; j < 4; j++) {
                    ulonglong2 uu = up[j];
                    ulonglong2 ww = wp[j];
                    // t = u + zbar*wneg ; dot += zbar * t   (= u*zbar - zbar^2*w)
                    unsigned long long tA0 = fma2(zpA[2*j],   ww.x, uu.x);
                    unsigned long long tA1 = fma2(zpA[2*j+1], ww.y, uu.y);
                    a0 = fma2(zpA[2*j],   tA0, a0);
                    a1 = fma2(zpA[2*j+1], tA1, a1);
                    unsigned long long tB0 = fma2(zpB[2*j],   ww.x, uu.x);
                    unsigned long long tB1 = fma2(zpB[2*j+1], ww.y, uu.y);
                    b0 = fma2(zpB[2*j],   tB0, b0);
                    b1 = fma2(zpB[2*j+1], tB1, b1);
                }
                float lo, hi;
                upk2(add2(a0, a1), lo, hi);
                sumA += exp2_fast(bA + an + lo + hi);
                upk2(add2(b0, b1), lo, hi);
                sumB += exp2_fast(bB + an + lo + hi);
            }
            if (p0 < NPAIR) {
                atomicAdd(&g_psi2[iA*Mm + jA], sumA);
                if (iA != jA) atomicAdd(&g_psi2[jA*Mm + iA], sumA);
            }
            if (p0 + 1 < NPAIR) {
                atomicAdd(&g_psi2[iB*Mm + jB], sumB);
                if (iB != jB) atomicAdd(&g_psi2[jB*Mm + iB], sumB);
            }
        } else {
            // ---- A-GEMM unit: psi1 on the fly + A += psi1^T y (packed) + KL ----
            float* zs        = (float*)SM;
            float (*sPP)[36] = (float(*)[36])(SM + 4096);
            float (*sP)[64]  = (float(*)[64])(SM + 22528);
            float* red       = (float*)(SM + 26624);
            int bb = u - 320;
            int d0 = (bb & 7) * 32;
            int n0 = (bb >> 3) * 128;
            ((float4*)zs)[tid] = ((const float4*)z)[tid];
            float kl = 0.f;
            if (tid < 128) {
                int n = n0 + tid;
                float lv2 = lg2(varp[0]);
                float prodD1 = 1.f, prodSg = 1.f, ss = 0.f;
                #pragma unroll
                for (int q = 0; q < Qq; q++) {
                    float mu = qmu[n*Qq + q];
                    float x  = qls[n*Qq + q];
                    float e  = ex2(-LOG2E * fabsf(x));
                    float sg = fmaxf(x, 0.f) + LN2f * lg2(1.0f + e);
                    float al = alpha[q];
                    ss += fmaf(sg, sg, mu*mu);
                    prodSg *= sg;
                    float d1 = fmaf(sg, al, 1.0f);
                    prodD1 *= d1;
                    float w1 = __fdividef(al, d1);
                    sPP[tid][q]      = mu;
                    sPP[tid][16 + q] = 0.5f * LOG2E * w1;
                }
                sPP[tid][32] = 2.0f*lv2 - 0.5f*lg2(prodD1);
                kl = -LN2f * lg2(prodSg) + 0.5f*(ss - (float)Qq);
            }
            __syncthreads();
            if ((bb & 7) == 0) {
                red[tid] = (tid < 128) ? kl : 0.f;
                __syncthreads();
                #pragma unroll
                for (int s = 128; s > 0; s >>= 1) { if (tid < s) red[tid] += red[tid+s]; __syncthreads(); }
                if (tid == 0) atomicAdd(&g_scal[0], red[0]);
                __syncthreads();
            }
            int jg = tid >> 5, dc = tid & 31;
            unsigned long long acc01 = 0, acc23 = 0, acc45 = 0, acc67 = 0;
            float yy = 0.f;
            for (int s = 0; s < 8; s++) {
                #pragma unroll
                for (int rr = 0; rr < 4; rr++) {
                    int e = tid + 256*rr;
                    int nn = e >> 6, j = e & 63;
                    const float* U = sPP[s*16 + nn];
                    float sacc = U[32];
                    #pragma unroll
                    for (int q = 0; q < Qq; q++) {
                        float dm = U[q] - zs[j*Qq + q];
                        sacc = fmaf(-U[16+q]*dm, dm, sacc);
                    }
                    sP[nn][j] = ex2(sacc);
                }
                __syncthreads();
                #pragma unroll
                for (int nn = 0; nn < 16; nn++) {
                    float yv = y[(n0 + s*16 + nn)*Dd + d0 + dc];
                    if (jg == 0) yy = fmaf(yv, yv, yy);
                    unsigned long long yd = pk2(yv, yv);
                    const ulonglong2* sp = (const ulonglong2*)&sP[nn][jg*8];
                    ulonglong2 pa = sp[0], pb = sp[1];
                    acc01 = fma2(yd, pa.x, acc01);
                    acc23 = fma2(yd, pa.y, acc23);
                    acc45 = fma2(yd, pb.x, acc45);
                    acc67 = fma2(yd, pb.y, acc67);
                }
                __syncthreads();
            }
            {
                float v0, v1;
                upk2(acc01, v0, v1);
                atomicAdd(&g_A[(jg*8 + 0)*Dd + d0 + dc], v0);
                atomicAdd(&g_A[(jg*8 + 1)*Dd + d0 + dc], v1);
                upk2(acc23, v0, v1);
                atomicAdd(&g_A[(jg*8 + 2)*Dd + d0 + dc], v0);
                atomicAdd(&g_A[(jg*8 + 3)*Dd + d0 + dc], v1);
                upk2(acc45, v0, v1);
                atomicAdd(&g_A[(jg*8 + 4)*Dd + d0 + dc], v0);
                atomicAdd(&g_A[(jg*8 + 5)*Dd + d0 + dc], v1);
                upk2(acc67, v0, v1);
                atomicAdd(&g_A[(jg*8 + 6)*Dd + d0 + dc], v0);
                atomicAdd(&g_A[(jg*8 + 7)*Dd + d0 + dc], v1);
            }
            red[tid] = yy; __syncthreads();
            #pragma unroll
            for (int s = 128; s > 0; s >>= 1) { if (tid < s) red[tid] += red[tid+s]; __syncthreads(); }
            if (tid == 0) atomicAdd(&g_scal[1], red[0]);
        }
    }

    grid_bar();

    // ===================== PHASE 2: G = A A^T (blocks 0..31) =================
    if (bx < 32) {
        float* a0s     = (float*)SM;
        float* a1s     = (float*)(SM + 1024);
        float (*sG)[8] = (float(*)[8])(SM + 2048);
        int r0 = bx * 2, r1 = r0 + 1;
        a0s[tid] = g_A[r0*Dd + tid];
        a1s[tid] = g_A[r1*Dd + tid];
        __syncthreads();
        int k = tid >> 2, q = tid & 3;
        const float4* bv4  = (const float4*)&g_A[k*Dd + q*64];
        const float4* av04 = (const float4*)&a0s[q*64];
        const float4* av14 = (const float4*)&a1s[q*64];
        float s0 = 0.f, s1 = 0.f;
        #pragma unroll
        for (int d = 0; d < 16; d++) {
            float4 b = bv4[d], a0 = av04[d], a1 = av14[d];
            s0 = fmaf(a0.x,b.x,s0); s0 = fmaf(a0.y,b.y,s0); s0 = fmaf(a0.z,b.z,s0); s0 = fmaf(a0.w,b.w,s0);
            s1 = fmaf(a1.x,b.x,s1); s1 = fmaf(a1.y,b.y,s1); s1 = fmaf(a1.z,b.z,s1); s1 = fmaf(a1.w,b.w,s1);
        }
        sG[k][q] = s0; sG[k][4 + q] = s1;
        __syncthreads();
        if (tid < 64)
            g_G[r0*Mm + tid] = sG[tid][0] + sG[tid][1] + sG[tid][2] + sG[tid][3];
        else if (tid < 128) {
            int t = tid - 64;
            g_G[r1*Mm + t] = sG[t][4] + sG[t][5] + sG[t][6] + sG[t][7];
        }
        __threadfence();
        __syncthreads();
        if (tid == 0) atomicAdd(&g_Gdone, 1u);
        return;
    }
    if (bx != 32) return;

    // ============ PHASE 3 (block 32): k_mm rebuild + dual rank-2 GJ ==========
    {
        float* zsh   = (float*)SM;
        float* sal   = (float*)(SM + 4096);
        float* SP    = (float*)(SM + 4352);    // [mat][buf][rowpair][64]
        float* asz   = (float*)(SM + 8448);
        float* wrow  = (float*)(SM + 12544);
        float* swarp = (float*)(SM + 12800);
        float* sres  = (float*)(SM + 12864);
        int mat  = tid >> 7;
        int t    = tid & 127;
        int r    = t >> 1;
        int h    = t & 1;
        int lane = tid & 31;
        float beta = 1.0f / softplus_f(noise[0]);
        float var  = varp[0];

        ((float4*)zsh)[tid] = ((const float4*)z)[tid];
        if (tid < Qq) sal[tid] = alpha[tid];
        __syncthreads();
        for (int e = tid; e < Mm*Qq; e += 256) asz[e] = sal[e & 15] * zsh[e];
        __syncthreads();
        if (tid < 64) {
            float w = 0.f;
            #pragma unroll
            for (int q = 0; q < Qq; q++) w = fmaf(asz[tid*Qq + q], zsh[tid*Qq + q], w);
            wrow[tid] = w;
        }
        __syncthreads();

        float c[32];
        {
            const float4* P4 = (const float4*)&g_psi2[r*64 + h*32];
            const float* ar = &asz[r*Qq];
            float wr = wrow[r];
            #pragma unroll
            for (int j4 = 0; j4 < 8; j4++) {
                float4 pv = P4[j4];
                float pl[4] = {pv.x, pv.y, pv.z, pv.w};
                #pragma unroll
                for (int l = 0; l < 4; l++) {
                    int col = h*32 + j4*4 + l;
                    float dot = 0.f;
                    #pragma unroll
                    for (int q = 0; q < Qq; q++) dot = fmaf(ar[q], zsh[col*Qq + q], dot);
                    float S = wr + wrow[col] - 2.0f*dot;
                    float v = var * ex2(-0.5f * LOG2E * S);
                    c[4*j4 + l] = mat ? fmaf(beta, pl[l], v) : v;
                }
            }
        }
        __syncthreads();

        float ld = 0.f;
        #pragma unroll
        for (int k = 0; k < 64; k += 2) {
            const int buf = (k >> 1) & 1;
            const int khalf = k >> 5;
            const int kk = k & 31;
            if (r == k || r == k + 1) {
                float4* s4 = (float4*)&SP[(((mat*2 + buf)*2) + (r - k))*64 + h*32];
                #pragma unroll
                for (int j4 = 0; j4 < 8; j4++)
                    s4[j4] = make_float4(c[4*j4], c[4*j4+1], c[4*j4+2], c[4*j4+3]);
            }
            asm volatile("bar.sync %0, 128;" :: "r"(1 + mat) : "memory");
            const float* R0 = &SP[((mat*2 + buf)*2 + 0)*64];
            const float* R1 = &SP[((mat*2 + buf)*2 + 1)*64];
            float R0k = R0[k], R0k1 = R0[k+1];
            float R1k = R1[k], R1k1 = R1[k+1];
            float rp0; asm("rcp.approx.f32 %0, %1;" : "=f"(rp0) : "f"(R0k));
            rp0 = rp0 * (2.0f - R0k * rp0);
            float g = R1k * rp0;
            float p1 = fmaf(-g, R0k1, R1k1);
            float rp1; asm("rcp.approx.f32 %0, %1;" : "=f"(rp1) : "f"(p1));
            rp1 = rp1 * (2.0f - p1 * rp1);
            ld += lg2(R0k) + lg2(p1);
            int src = (lane & ~1) | khalf;
            float f0 = __shfl_sync(0xffffffffu, c[kk],   src);
            float m1 = __shfl_sync(0xffffffffu, c[kk+1], src);
            float b0, b1, s;
            if (r == k) {
                float fr1k = rp0 * R0k1 * rp1;
                b0 = -fmaf(fr1k, g, rp0);  b1 = fr1k;   s = 0.f;
            } else if (r == k + 1) {
                b0 = rp1 * g;              b1 = -rp1;   s = 0.f;
            } else {
                float fr0 = f0 * rp0;
                float f1 = fmaf(-fr0, R0k1, m1);
                float fr1 = f1 * rp1;
                b0 = fmaf(-fr1, g, fr0);   b1 = fr1;    s = 1.f;
            }
            const float4* P04 = (const float4*)&R0[h*32];
            const float4* P14 = (const float4*)&R1[h*32];
            #pragma unroll
            for (int j4 = 0; j4 < 8; j4++) {
                float4 q0 = P04[j4], q1 = P14[j4];
                c[4*j4+0] = fmaf(-b1, q1.x, fmaf(-b0, q0.x, s*c[4*j4+0]));
                c[4*j4+1] = fmaf(-b1, q1.y, fmaf(-b0, q0.y, s*c[4*j4+1]));
                c[4*j4+2] = fmaf(-b1, q1.z, fmaf(-b0, q0.z, s*c[4*j4+2]));
                c[4*j4+3] = fmaf(-b1, q1.w, fmaf(-b0, q0.w, s*c[4*j4+3]));
            }
            if (khalf == h) { c[kk] = -b0; c[kk+1] = -b1; }
        }

        if (tid == 0) { while (atomicAdd(&g_Gdone, 0u) < 32u) __nanosleep(64); }
        __syncthreads();
        __threadfence();

        const float4* T4 = (const float4*)((mat ? g_G : g_psi2) + r*64 + h*32);
        float tr = 0.f;
        #pragma unroll
        for (int j4 = 0; j4 < 8; j4++) {
            float4 tv = T4[j4];
            tr = fmaf(c[4*j4+0], tv.x, tr); tr = fmaf(c[4*j4+1], tv.y, tr);
            tr = fmaf(c[4*j4+2], tv.z, tr); tr = fmaf(c[4*j4+3], tv.w, tr);
        }
        #pragma unroll
        for (int sft = 16; sft > 0; sft >>= 1) tr += __shfl_xor_sync(0xffffffffu, tr, sft);
        if (lane == 0) swarp[tid >> 5] = tr;
        if (t == 0)    sres[mat] = ld * LN2f;
        // snapshot scalars BEFORE the zeroing pass
        float klsum = g_scal[0];
        float yysum = g_scal[1];
        __syncthreads();

        // ---- zero accumulators for next graph replay ----
        float4 z4 = make_float4(0.f, 0.f, 0.f, 0.f);
        for (int i = tid; i < 4096; i += 256) ((float4*)g_A)[i] = z4;
        for (int i = tid; i < 1024; i += 256) ((float4*)g_psi2)[i] = z4;
        if (tid < 8) g_scal[tid] = 0.f;
        if (tid == 9) g_Gdone = 0u;

        if (tid == 0) {
            float tr0 = swarp[0] + swarp[1] + swarp[2] + swarp[3];
            float tr1 = swarp[4] + swarp[5] + swarp[6] + swarp[7];
            double kl = (double)klsum / ((double)Nn * (double)Dd);
            double nd = (double)Nn * (double)Dd;
            double F = 0.5 * Nn * log((double)beta)
                     + 0.5 * (double)sres[0]
                     - 0.5 * Nn * log(3.14159265358979323846)
                     - 0.5 * (double)sres[1]
                     - 0.5 * (double)beta * ((double)Nn * (double)var)
                     + 0.5 * (double)tr0;
            double tr_yWy = (double)beta * (double)yysum - (double)tr1;
            F = (F * Dd - 0.5 * tr_yWy) / nd;
            out[0] = (float)(F - kl);
        }
    }
}

extern "C" void kernel_launch(void* const* d_in, const int* in_sizes, int n_in,
                              void* d_out, int out_size) {
    const float* y     = (const float*)d_in[0];
    const float* qmu   = (const float*)d_in[1];
    const float* qls   = (const float*)d_in[2];
    const float* z     = (const float*)d_in[3];
    const float* noise = (const float*)d_in[4];
    const float* alpha = (const float*)d_in[5];
    const float* varp  = (const float*)d_in[6];
    float* out = (float*)d_out;

    fused<<<NBLK, 256>>>(y, qmu, qls, z, noise, alpha, varp, out);
}

// round 13
// speedup vs baseline: 1.0816x; 1.0816x over previous
#include <cuda_runtime.h>
#include <math.h>

#define Nn 2048
#define Dd 256
#define Qq 16
#define Mm 64
#define MMs 4096
#define NPAIR 2080
#define NBLK 288
#define LOG2E 1.4426950408889634f
#define LN2f  0.6931471805599453f

// -------- scratch (device globals; zero at load, re-zeroed by GJ tail) -----
__device__ alignas(16) float g_psi2[MMs];
__device__ alignas(16) float g_A[Mm*Dd];
__device__ alignas(16) float g_G[MMs];
__device__ float  g_scal[8];          // [0]=KL sum, [1]=sum(y*y)
__device__ unsigned g_Gdone;
__device__ unsigned g_cnt;
__device__ volatile unsigned g_gen;

__device__ __forceinline__ float softplus_f(float x) {
    float ax = fabsf(x);
    return fmaxf(x, 0.0f) + log1pf(__expf(-ax));
}
__device__ __forceinline__ float ex2(float x) {
    float y; asm("ex2.approx.f32 %0, %1;" : "=f"(y) : "f"(x)); return y;
}
__device__ __forceinline__ float lg2(float x) {
    float y; asm("lg2.approx.f32 %0, %1;" : "=f"(y) : "f"(x)); return y;
}
// FMA-pipe exp2 (psi2 hot loop; avoids MUFU wall). |rel err| ~2.4e-6
__device__ __forceinline__ float exp2_fast(float x) {
    x = fmaxf(x, -125.0f);
    float r = rintf(x);
    float f = x - r;
    int   i = (int)r;
    float p =          1.3333558146e-3f;
    p = fmaf(p, f,     9.6181291076e-3f);
    p = fmaf(p, f,     5.5504108664e-2f);
    p = fmaf(p, f,     2.4022650696e-1f);
    p = fmaf(p, f,     6.9314718056e-1f);
    p = fmaf(p, f,     1.0f);
    return __int_as_float(__float_as_int(p) + (i << 23));
}

// ---- packed f32x2 helpers ----
__device__ __forceinline__ unsigned long long pk2(float lo, float hi) {
    unsigned long long r;
    asm("mov.b64 %0, {%1, %2};" : "=l"(r) : "f"(lo), "f"(hi));
    return r;
}
__device__ __forceinline__ void upk2(unsigned long long v, float& lo, float& hi) {
    asm("mov.b64 {%0, %1}, %2;" : "=f"(lo), "=f"(hi) : "l"(v));
}
__device__ __forceinline__ unsigned long long fma2(unsigned long long a,
                                                   unsigned long long b,
                                                   unsigned long long c) {
    unsigned long long d;
    asm("fma.rn.f32x2 %0, %1, %2, %3;" : "=l"(d) : "l"(a), "l"(b), "l"(c));
    return d;
}
__device__ __forceinline__ unsigned long long add2(unsigned long long a,
                                                   unsigned long long b) {
    unsigned long long d;
    asm("add.rn.f32x2 %0, %1, %2;" : "=l"(d) : "l"(a), "l"(b));
    return d;
}

__device__ __forceinline__ int tri_base(int i) { return i*Mm - ((i*(i-1)) >> 1); }
__device__ __forceinline__ void pair_ij(int p, int& io, int& jo) {
    int ii = (int)(0.5f*(129.0f - sqrtf(fmaf(-8.f, (float)p, 16641.f))));
    while (tri_base(ii+1) <= p) ii++;
    while (tri_base(ii)   >  p) ii--;
    io = ii;
    jo = p - tri_base(ii) + ii;
}

// grid-wide barrier (288 co-resident blocks at 2 CTA/SM)
__device__ __forceinline__ void grid_bar() {
    __threadfence();
    __syncthreads();
    if (threadIdx.x == 0) {
        unsigned gen = g_gen;
        if (atomicAdd(&g_cnt, 1u) == NBLK - 1u) {
            g_cnt = 0u;
            __threadfence();
            g_gen = gen + 1u;
        } else {
            while (g_gen == gen) __nanosleep(32);
        }
    }
    __syncthreads();
    __threadfence();
}

__global__ void __launch_bounds__(256, 2) fused(
        const float* __restrict__ y,    const float* __restrict__ qmu,
        const float* __restrict__ qls,  const float* __restrict__ z,
        const float* __restrict__ noise,const float* __restrict__ alpha,
        const float* __restrict__ varp, float* __restrict__ out) {
    __shared__ alignas(16) char SM[27648];
    const int bx = blockIdx.x, tid = threadIdx.x;

    // ===================== PHASE 1 =====================
    if (bx < 160) {
        // ---- psi2 unit: pg=bx>>5 → 512 pair-slots; 64 n rows per block ----
        // row layout (144B): u'[16] @0, wneg'[16] @64B, a' @128B
        float* zsh  = (float*)SM;              // 1024 f
        float* sal  = (float*)(SM + 4096);     // 16 f
        float* sR2f = (float*)(SM + 4224);     // 64 rows x 144B
        ((float4*)zsh)[tid] = ((const float4*)z)[tid];
        if (tid < Qq) sal[tid] = alpha[tid];
        __syncthreads();
        int pg = bx >> 5, ny = bx & 31;
        int n0 = ny * 64;
        if (tid < 64) {
            int n = n0 + tid;
            float lv2 = lg2(varp[0]);
            float prodD2 = 1.f, P = 0.f;
            float* rw = &sR2f[tid*36];
            #pragma unroll
            for (int q = 0; q < Qq; q++) {
                float mu = qmu[n*Qq + q];
                float x  = qls[n*Qq + q];
                float e  = ex2(-LOG2E * fabsf(x));
                float sg = fmaxf(x, 0.f) + LN2f * lg2(1.0f + e);
                float al = sal[q];
                float d2 = fmaf(2.0f*al, sg, 1.0f);
                prodD2 *= d2;
                float w2 = __fdividef(al, d2);
                P += w2*mu*mu;
                rw[q]      = LOG2E * 2.0f * w2 * mu;   // u'_q
                rw[16 + q] = -LOG2E * w2;              // wneg'_q
            }
            rw[32] = 4.0f*lv2 - 0.5f*lg2(prodD2) - LOG2E * P;  // a'_n
        }
        int p0 = (pg*256 + tid)*2;
        int iA, jA, iB, jB;
        pair_ij(min(p0,   NPAIR-1), iA, jA);
        pair_ij(min(p0+1, NPAIR-1), iB, jB);
        unsigned long long zpA[8], zpB[8];
        float bA, bB;
        {
            float S = 0.f;
            #pragma unroll
            for (int k = 0; k < 4; k++) {
                float4 zi = ((const float4*)(zsh + iA*Qq))[k];
                float4 zj = ((const float4*)(zsh + jA*Qq))[k];
                zpA[2*k]   = pk2(0.5f*(zi.x+zj.x), 0.5f*(zi.y+zj.y));
                zpA[2*k+1] = pk2(0.5f*(zi.z+zj.z), 0.5f*(zi.w+zj.w));
                float dx = zi.x-zj.x, dy = zi.y-zj.y, dz = zi.z-zj.z, dw = zi.w-zj.w;
                S = fmaf(sal[4*k+0]*dx, dx, S); S = fmaf(sal[4*k+1]*dy, dy, S);
                S = fmaf(sal[4*k+2]*dz, dz, S); S = fmaf(sal[4*k+3]*dw, dw, S);
            }
            bA = -0.25f * LOG2E * S;
        }
        {
            float S = 0.f;
            #pragma unroll
            for (int k = 0; k < 4; k++) {
                float4 zi = ((const float4*)(zsh + iB*Qq))[k];
                float4 zj = ((const float4*)(zsh + jB*Qq))[k];
                zpB[2*k]   = pk2(0.5f*(zi.x+zj.x), 0.5f*(zi.y+zj.y));
                zpB[2*k+1] = pk2(0.5f*(zi.z+zj.z), 0.5f*(zi.w+zj.w));
                float dx = zi.x-zj.x, dy = zi.y-zj.y, dz = zi.z-zj.z, dw = zi.w-zj.w;
                S = fmaf(sal[4*k+0]*dx, dx, S); S = fmaf(sal[4*k+1]*dy, dy, S);
                S = fmaf(sal[4*k+2]*dz, dz, S); S = fmaf(sal[4*k+3]*dw, dw, S);
            }
            bB = -0.25f * LOG2E * S;
        }
        __syncthreads();
        float sumA = 0.f, sumB = 0.f;
        #pragma unroll 4
        for (int i = 0; i < 64; i++) {
            const char* rowp = (const char*)sR2f + i*144;
            const ulonglong2* up = (const ulonglong2*)rowp;        // u packed
            const ulonglong2* wp = (const ulonglong2*)(rowp + 64); // wneg packed
            float an = ((const float*)rowp)[32];
            unsigned long long a0 = 0, a1 = 0, b0 = 0, b1 = 0;
            #pragma unroll
            for (int j = 0; j < 4; j++) {
                ulonglong2 uu = up[j];
                ulonglong2 ww = wp[j];
                // t = u + zbar*wneg ; dot += zbar * t   (= u*zbar - zbar^2*w)
                unsigned long long tA0 = fma2(zpA[2*j],   ww.x, uu.x);
                unsigned long long tA1 = fma2(zpA[2*j+1], ww.y, uu.y);
                a0 = fma2(zpA[2*j],   tA0, a0);
                a1 = fma2(zpA[2*j+1], tA1, a1);
                unsigned long long tB0 = fma2(zpB[2*j],   ww.x, uu.x);
                unsigned long long tB1 = fma2(zpB[2*j+1], ww.y, uu.y);
                b0 = fma2(zpB[2*j],   tB0, b0);
                b1 = fma2(zpB[2*j+1], tB1, b1);
            }
            float lo, hi;
            upk2(add2(a0, a1), lo, hi);
            sumA += exp2_fast(bA + an + lo + hi);
            upk2(add2(b0, b1), lo, hi);
            sumB += exp2_fast(bB + an + lo + hi);
        }
        if (p0 < NPAIR) {
            atomicAdd(&g_psi2[iA*Mm + jA], sumA);
            if (iA != jA) atomicAdd(&g_psi2[jA*Mm + iA], sumA);
        }
        if (p0 + 1 < NPAIR) {
            atomicAdd(&g_psi2[iB*Mm + jB], sumB);
            if (iB != jB) atomicAdd(&g_psi2[jB*Mm + iB], sumB);
        }
    } else {
        // ---- A-GEMM unit: psi1 on the fly + A += psi1^T y (packed) + KL ----
        float* zs        = (float*)SM;
        float (*sPP)[36] = (float(*)[36])(SM + 4096);
        float (*sP)[64]  = (float(*)[64])(SM + 22528);
        float* red       = (float*)(SM + 26624);
        int bb = bx - 160;
        int d0 = (bb & 7) * 32;
        int n0 = (bb >> 3) * 128;
        ((float4*)zs)[tid] = ((const float4*)z)[tid];
        float kl = 0.f;
        if (tid < 128) {
            int n = n0 + tid;
            float lv2 = lg2(varp[0]);
            float prodD1 = 1.f, prodSg = 1.f, ss = 0.f;
            #pragma unroll
            for (int q = 0; q < Qq; q++) {
                float mu = qmu[n*Qq + q];
                float x  = qls[n*Qq + q];
                float e  = ex2(-LOG2E * fabsf(x));
                float sg = fmaxf(x, 0.f) + LN2f * lg2(1.0f + e);
                float al = alpha[q];
                ss += fmaf(sg, sg, mu*mu);
                prodSg *= sg;
                float d1 = fmaf(sg, al, 1.0f);
                prodD1 *= d1;
                float w1 = __fdividef(al, d1);
                sPP[tid][q]      = mu;
                sPP[tid][16 + q] = 0.5f * LOG2E * w1;
            }
            sPP[tid][32] = 2.0f*lv2 - 0.5f*lg2(prodD1);
            kl = -LN2f * lg2(prodSg) + 0.5f*(ss - (float)Qq);
        }
        __syncthreads();
        if ((bb & 7) == 0) {
            red[tid] = (tid < 128) ? kl : 0.f;
            __syncthreads();
            #pragma unroll
            for (int s = 128; s > 0; s >>= 1) { if (tid < s) red[tid] += red[tid+s]; __syncthreads(); }
            if (tid == 0) atomicAdd(&g_scal[0], red[0]);
            __syncthreads();
        }
        int jg = tid >> 5, dc = tid & 31;
        unsigned long long acc01 = 0, acc23 = 0, acc45 = 0, acc67 = 0;
        float yy = 0.f;
        for (int s = 0; s < 8; s++) {
            #pragma unroll
            for (int rr = 0; rr < 4; rr++) {
                int e = tid + 256*rr;
                int nn = e >> 6, j = e & 63;
                const float* U = sPP[s*16 + nn];
                float sacc = U[32];
                #pragma unroll
                for (int q = 0; q < Qq; q++) {
                    float dm = U[q] - zs[j*Qq + q];
                    sacc = fmaf(-U[16+q]*dm, dm, sacc);
                }
                sP[nn][j] = ex2(sacc);
            }
            __syncthreads();
            #pragma unroll
            for (int nn = 0; nn < 16; nn++) {
                float yv = y[(n0 + s*16 + nn)*Dd + d0 + dc];
                if (jg == 0) yy = fmaf(yv, yv, yy);
                unsigned long long yd = pk2(yv, yv);
                const ulonglong2* sp = (const ulonglong2*)&sP[nn][jg*8];
                ulonglong2 pa = sp[0], pb = sp[1];
                acc01 = fma2(yd, pa.x, acc01);
                acc23 = fma2(yd, pa.y, acc23);
                acc45 = fma2(yd, pb.x, acc45);
                acc67 = fma2(yd, pb.y, acc67);
            }
            __syncthreads();
        }
        {
            float v0, v1;
            upk2(acc01, v0, v1);
            atomicAdd(&g_A[(jg*8 + 0)*Dd + d0 + dc], v0);
            atomicAdd(&g_A[(jg*8 + 1)*Dd + d0 + dc], v1);
            upk2(acc23, v0, v1);
            atomicAdd(&g_A[(jg*8 + 2)*Dd + d0 + dc], v0);
            atomicAdd(&g_A[(jg*8 + 3)*Dd + d0 + dc], v1);
            upk2(acc45, v0, v1);
            atomicAdd(&g_A[(jg*8 + 4)*Dd + d0 + dc], v0);
            atomicAdd(&g_A[(jg*8 + 5)*Dd + d0 + dc], v1);
            upk2(acc67, v0, v1);
            atomicAdd(&g_A[(jg*8 + 6)*Dd + d0 + dc], v0);
            atomicAdd(&g_A[(jg*8 + 7)*Dd + d0 + dc], v1);
        }
        red[tid] = yy; __syncthreads();
        #pragma unroll
        for (int s = 128; s > 0; s >>= 1) { if (tid < s) red[tid] += red[tid+s]; __syncthreads(); }
        if (tid == 0) atomicAdd(&g_scal[1], red[0]);
    }

    grid_bar();

    // ===================== PHASE 2: G = A A^T (blocks 0..31) =================
    if (bx < 32) {
        float* a0s     = (float*)SM;
        float* a1s     = (float*)(SM + 1024);
        float (*sG)[8] = (float(*)[8])(SM + 2048);
        int r0 = bx * 2, r1 = r0 + 1;
        a0s[tid] = g_A[r0*Dd + tid];
        a1s[tid] = g_A[r1*Dd + tid];
        __syncthreads();
        int k = tid >> 2, q = tid & 3;
        const float4* bv4  = (const float4*)&g_A[k*Dd + q*64];
        const float4* av04 = (const float4*)&a0s[q*64];
        const float4* av14 = (const float4*)&a1s[q*64];
        float s0 = 0.f, s1 = 0.f;
        #pragma unroll
        for (int d = 0; d < 16; d++) {
            float4 b = bv4[d], a0 = av04[d], a1 = av14[d];
            s0 = fmaf(a0.x,b.x,s0); s0 = fmaf(a0.y,b.y,s0); s0 = fmaf(a0.z,b.z,s0); s0 = fmaf(a0.w,b.w,s0);
            s1 = fmaf(a1.x,b.x,s1); s1 = fmaf(a1.y,b.y,s1); s1 = fmaf(a1.z,b.z,s1); s1 = fmaf(a1.w,b.w,s1);
        }
        sG[k][q] = s0; sG[k][4 + q] = s1;
        __syncthreads();
        if (tid < 64)
            g_G[r0*Mm + tid] = sG[tid][0] + sG[tid][1] + sG[tid][2] + sG[tid][3];
        else if (tid < 128) {
            int t = tid - 64;
            g_G[r1*Mm + t] = sG[t][4] + sG[t][5] + sG[t][6] + sG[t][7];
        }
        __threadfence();
        __syncthreads();
        if (tid == 0) atomicAdd(&g_Gdone, 1u);
        return;
    }
    if (bx != 32) return;

    // ============ PHASE 3 (block 32): k_mm rebuild + dual rank-2 GJ ==========
    {
        float* zsh   = (float*)SM;
        float* sal   = (float*)(SM + 4096);
        float* SP    = (float*)(SM + 4352);    // [mat][buf][rowpair][64]
        float* asz   = (float*)(SM + 8448);
        float* wrow  = (float*)(SM + 12544);
        float* swarp = (float*)(SM + 12800);
        float* sres  = (float*)(SM + 12864);
        int mat  = tid >> 7;
        int t    = tid & 127;
        int r    = t >> 1;
        int h    = t & 1;
        int lane = tid & 31;
        float beta = 1.0f / softplus_f(noise[0]);
        float var  = varp[0];

        ((float4*)zsh)[tid] = ((const float4*)z)[tid];
        if (tid < Qq) sal[tid] = alpha[tid];
        __syncthreads();
        for (int e = tid; e < Mm*Qq; e += 256) asz[e] = sal[e & 15] * zsh[e];
        __syncthreads();
        if (tid < 64) {
            float w = 0.f;
            #pragma unroll
            for (int q = 0; q < Qq; q++) w = fmaf(asz[tid*Qq + q], zsh[tid*Qq + q], w);
            wrow[tid] = w;
        }
        __syncthreads();

        float c[32];
        {
            const float4* P4 = (const float4*)&g_psi2[r*64 + h*32];
            const float* ar = &asz[r*Qq];
            float wr = wrow[r];
            #pragma unroll
            for (int j4 = 0; j4 < 8; j4++) {
                float4 pv = P4[j4];
                float pl[4] = {pv.x, pv.y, pv.z, pv.w};
                #pragma unroll
                for (int l = 0; l < 4; l++) {
                    int col = h*32 + j4*4 + l;
                    float dot = 0.f;
                    #pragma unroll
                    for (int q = 0; q < Qq; q++) dot = fmaf(ar[q], zsh[col*Qq + q], dot);
                    float S = wr + wrow[col] - 2.0f*dot;
                    float v = var * ex2(-0.5f * LOG2E * S);
                    c[4*j4 + l] = mat ? fmaf(beta, pl[l], v) : v;
                }
            }
        }
        __syncthreads();

        float ld = 0.f;
        #pragma unroll
        for (int k = 0; k < 64; k += 2) {
            const int buf = (k >> 1) & 1;
            const int khalf = k >> 5;
            const int kk = k & 31;
            if (r == k || r == k + 1) {
                float4* s4 = (float4*)&SP[(((mat*2 + buf)*2) + (r - k))*64 + h*32];
                #pragma unroll
                for (int j4 = 0; j4 < 8; j4++)
                    s4[j4] = make_float4(c[4*j4], c[4*j4+1], c[4*j4+2], c[4*j4+3]);
            }
            asm volatile("bar.sync %0, 128;" :: "r"(1 + mat) : "memory");
            const float* R0 = &SP[((mat*2 + buf)*2 + 0)*64];
            const float* R1 = &SP[((mat*2 + buf)*2 + 1)*64];
            float R0k = R0[k], R0k1 = R0[k+1];
            float R1k = R1[k], R1k1 = R1[k+1];
            float rp0; asm("rcp.approx.f32 %0, %1;" : "=f"(rp0) : "f"(R0k));
            rp0 = rp0 * (2.0f - R0k * rp0);
            float g = R1k * rp0;
            float p1 = fmaf(-g, R0k1, R1k1);
            float rp1; asm("rcp.approx.f32 %0, %1;" : "=f"(rp1) : "f"(p1));
            rp1 = rp1 * (2.0f - p1 * rp1);
            ld += lg2(R0k) + lg2(p1);
            int src = (lane & ~1) | khalf;
            float f0 = __shfl_sync(0xffffffffu, c[kk],   src);
            float m1 = __shfl_sync(0xffffffffu, c[kk+1], src);
            float b0, b1, s;
            if (r == k) {
                float fr1k = rp0 * R0k1 * rp1;
                b0 = -fmaf(fr1k, g, rp0);  b1 = fr1k;   s = 0.f;
            } else if (r == k + 1) {
                b0 = rp1 * g;              b1 = -rp1;   s = 0.f;
            } else {
                float fr0 = f0 * rp0;
                float f1 = fmaf(-fr0, R0k1, m1);
                float fr1 = f1 * rp1;
                b0 = fmaf(-fr1, g, fr0);   b1 = fr1;    s = 1.f;
            }
            const float4* P04 = (const float4*)&R0[h*32];
            const float4* P14 = (const float4*)&R1[h*32];
            #pragma unroll
            for (int j4 = 0; j4 < 8; j4++) {
                float4 q0 = P04[j4], q1 = P14[j4];
                c[4*j4+0] = fmaf(-b1, q1.x, fmaf(-b0, q0.x, s*c[4*j4+0]));
                c[4*j4+1] = fmaf(-b1, q1.y, fmaf(-b0, q0.y, s*c[4*j4+1]));
                c[4*j4+2] = fmaf(-b1, q1.z, fmaf(-b0, q0.z, s*c[4*j4+2]));
                c[4*j4+3] = fmaf(-b1, q1.w, fmaf(-b0, q0.w, s*c[4*j4+3]));
            }
            if (khalf == h) { c[kk] = -b0; c[kk+1] = -b1; }
        }

        if (tid == 0) { while (atomicAdd(&g_Gdone, 0u) < 32u) __nanosleep(64); }
        __syncthreads();
        __threadfence();

        const float4* T4 = (const float4*)((mat ? g_G : g_psi2) + r*64 + h*32);
        float tr = 0.f;
        #pragma unroll
        for (int j4 = 0; j4 < 8; j4++) {
            float4 tv = T4[j4];
            tr = fmaf(c[4*j4+0], tv.x, tr); tr = fmaf(c[4*j4+1], tv.y, tr);
            tr = fmaf(c[4*j4+2], tv.z, tr); tr = fmaf(c[4*j4+3], tv.w, tr);
        }
        #pragma unroll
        for (int sft = 16; sft > 0; sft >>= 1) tr += __shfl_xor_sync(0xffffffffu, tr, sft);
        if (lane == 0) swarp[tid >> 5] = tr;
        if (t == 0)    sres[mat] = ld * LN2f;
        // snapshot scalars BEFORE the zeroing pass
        float klsum = g_scal[0];
        float yysum = g_scal[1];
        __syncthreads();

        // ---- zero accumulators for next graph replay ----
        float4 z4 = make_float4(0.f, 0.f, 0.f, 0.f);
        for (int i = tid; i < 4096; i += 256) ((float4*)g_A)[i] = z4;
        for (int i = tid; i < 1024; i += 256) ((float4*)g_psi2)[i] = z4;
        if (tid < 8) g_scal[tid] = 0.f;
        if (tid == 9) g_Gdone = 0u;

        if (tid == 0) {
            float tr0 = swarp[0] + swarp[1] + swarp[2] + swarp[3];
            float tr1 = swarp[4] + swarp[5] + swarp[6] + swarp[7];
            double kl = (double)klsum / ((double)Nn * (double)Dd);
            double nd = (double)Nn * (double)Dd;
            double F = 0.5 * Nn * log((double)beta)
                     + 0.5 * (double)sres[0]
                     - 0.5 * Nn * log(3.14159265358979323846)
                     - 0.5 * (double)sres[1]
                     - 0.5 * (double)beta * ((double)Nn * (double)var)
                     + 0.5 * (double)tr0;
            double tr_yWy = (double)beta * (double)yysum - (double)tr1;
            F = (F * Dd - 0.5 * tr_yWy) / nd;
            out[0] = (float)(F - kl);
        }
    }
}

extern "C" void kernel_launch(void* const* d_in, const int* in_sizes, int n_in,
                              void* d_out, int out_size) {
    const float* y     = (const float*)d_in[0];
    const float* qmu   = (const float*)d_in[1];
    const float* qls   = (const float*)d_in[2];
    const float* z     = (const float*)d_in[3];
    const float* noise = (const float*)d_in[4];
    const float* alpha = (const float*)d_in[5];
    const float* varp  = (const float*)d_in[6];
    float* out = (float*)d_out;

    fused<<<NBLK, 256>>>(y, qmu, qls, z, noise, alpha, varp, out);
}

// round 14
// speedup vs baseline: 1.1218x; 1.0372x over previous
#include <cuda_runtime.h>
#include <math.h>

#define Nn 2048
#define Dd 256
#define Qq 16
#define Mm 64
#define MMs 4096
#define NPAIR 2080
#define NBLK 289
#define LOG2E 1.4426950408889634f
#define LN2f  0.6931471805599453f

// -------- scratch (device globals; zero at load, re-zeroed by tail) -----
__device__ alignas(16) float g_psi2[MMs];
__device__ alignas(16) float g_A[Mm*Dd];
__device__ alignas(16) float g_G[MMs];
__device__ float  g_scal[8];          // [0]=KL sum, [1]=sum(y*y)
__device__ float  g_res[4];           // [0]=ld0, [1]=tr0 (from block 288)
__device__ unsigned g_Gdone;
__device__ unsigned g_R0done;
__device__ unsigned g_cnt;
__device__ volatile unsigned g_gen;

__device__ __forceinline__ float softplus_f(float x) {
    float ax = fabsf(x);
    return fmaxf(x, 0.0f) + log1pf(__expf(-ax));
}
__device__ __forceinline__ float ex2(float x) {
    float y; asm("ex2.approx.f32 %0, %1;" : "=f"(y) : "f"(x)); return y;
}
__device__ __forceinline__ float lg2(float x) {
    float y; asm("lg2.approx.f32 %0, %1;" : "=f"(y) : "f"(x)); return y;
}
// FMA-pipe exp2 (psi2 hot loop; avoids MUFU wall). |rel err| ~2.4e-6
__device__ __forceinline__ float exp2_fast(float x) {
    x = fmaxf(x, -125.0f);
    float r = rintf(x);
    float f = x - r;
    int   i = (int)r;
    float p =          1.3333558146e-3f;
    p = fmaf(p, f,     9.6181291076e-3f);
    p = fmaf(p, f,     5.5504108664e-2f);
    p = fmaf(p, f,     2.4022650696e-1f);
    p = fmaf(p, f,     6.9314718056e-1f);
    p = fmaf(p, f,     1.0f);
    return __int_as_float(__float_as_int(p) + (i << 23));
}

// ---- packed f32x2 helpers ----
__device__ __forceinline__ unsigned long long pk2(float lo, float hi) {
    unsigned long long r;
    asm("mov.b64 %0, {%1, %2};" : "=l"(r) : "f"(lo), "f"(hi));
    return r;
}
__device__ __forceinline__ void upk2(unsigned long long v, float& lo, float& hi) {
    asm("mov.b64 {%0, %1}, %2;" : "=f"(lo), "=f"(hi) : "l"(v));
}
__device__ __forceinline__ unsigned long long fma2(unsigned long long a,
                                                   unsigned long long b,
                                                   unsigned long long c) {
    unsigned long long d;
    asm("fma.rn.f32x2 %0, %1, %2, %3;" : "=l"(d) : "l"(a), "l"(b), "l"(c));
    return d;
}
__device__ __forceinline__ unsigned long long add2(unsigned long long a,
                                                   unsigned long long b) {
    unsigned long long d;
    asm("add.rn.f32x2 %0, %1, %2;" : "=l"(d) : "l"(a), "l"(b));
    return d;
}

__device__ __forceinline__ int tri_base(int i) { return i*Mm - ((i*(i-1)) >> 1); }
__device__ __forceinline__ void pair_ij(int p, int& io, int& jo) {
    int ii = (int)(0.5f*(129.0f - sqrtf(fmaf(-8.f, (float)p, 16641.f))));
    while (tri_base(ii+1) <= p) ii++;
    while (tri_base(ii)   >  p) ii--;
    io = ii;
    jo = p - tri_base(ii) + ii;
}

// grid-wide barrier (289 co-resident blocks at 2 CTA/SM)
__device__ __forceinline__ void grid_bar() {
    __threadfence();
    __syncthreads();
    if (threadIdx.x == 0) {
        unsigned gen = g_gen;
        if (atomicAdd(&g_cnt, 1u) == NBLK - 1u) {
            g_cnt = 0u;
            __threadfence();
            g_gen = gen + 1u;
        } else {
            while (g_gen == gen) __nanosleep(32);
        }
    }
    __syncthreads();
    __threadfence();
}

// half-row Gauss-Jordan on a 64x64 SPD matrix distributed as 128 threads x
// 32-col half-rows. SP = caller's 256-float pivot region (2 bufs x 2 rows x 64).
// Returns log2-det accumulated identically on every participating thread.
__device__ __forceinline__ float gj_run(float* SP, float c[32],
                                        int r, int h, int lane) {
    float ld = 0.f;
    #pragma unroll
    for (int k = 0; k < 64; k += 2) {
        const int buf = (k >> 1) & 1;
        const int khalf = k >> 5;
        const int kk = k & 31;
        if (r == k || r == k + 1) {
            float4* s4 = (float4*)&SP[(buf*2 + (r - k))*64 + h*32];
            #pragma unroll
            for (int j4 = 0; j4 < 8; j4++)
                s4[j4] = make_float4(c[4*j4], c[4*j4+1], c[4*j4+2], c[4*j4+3]);
        }
        asm volatile("bar.sync 1, 128;" ::: "memory");
        const float* R0 = &SP[(buf*2 + 0)*64];
        const float* R1 = &SP[(buf*2 + 1)*64];
        float R0k = R0[k], R0k1 = R0[k+1];
        float R1k = R1[k], R1k1 = R1[k+1];
        float rp0; asm("rcp.approx.f32 %0, %1;" : "=f"(rp0) : "f"(R0k));
        rp0 = rp0 * (2.0f - R0k * rp0);
        float g = R1k * rp0;
        float p1 = fmaf(-g, R0k1, R1k1);
        float rp1; asm("rcp.approx.f32 %0, %1;" : "=f"(rp1) : "f"(p1));
        rp1 = rp1 * (2.0f - p1 * rp1);
        ld += lg2(R0k) + lg2(p1);
        int src = (lane & ~1) | khalf;
        float f0 = __shfl_sync(0xffffffffu, c[kk],   src);
        float m1 = __shfl_sync(0xffffffffu, c[kk+1], src);
        float b0, b1, s;
        if (r == k) {
            float fr1k = rp0 * R0k1 * rp1;
            b0 = -fmaf(fr1k, g, rp0);  b1 = fr1k;   s = 0.f;
        } else if (r == k + 1) {
            b0 = rp1 * g;              b1 = -rp1;   s = 0.f;
        } else {
            float fr0 = f0 * rp0;
            float f1 = fmaf(-fr0, R0k1, m1);
            float fr1 = f1 * rp1;
            b0 = fmaf(-fr1, g, fr0);   b1 = fr1;    s = 1.f;
        }
        const float4* P04 = (const float4*)&R0[h*32];
        const float4* P14 = (const float4*)&R1[h*32];
        #pragma unroll
        for (int j4 = 0; j4 < 8; j4++) {
            float4 q0 = P04[j4], q1 = P14[j4];
            c[4*j4+0] = fmaf(-b1, q1.x, fmaf(-b0, q0.x, s*c[4*j4+0]));
            c[4*j4+1] = fmaf(-b1, q1.y, fmaf(-b0, q0.y, s*c[4*j4+1]));
            c[4*j4+2] = fmaf(-b1, q1.z, fmaf(-b0, q0.z, s*c[4*j4+2]));
            c[4*j4+3] = fmaf(-b1, q1.w, fmaf(-b0, q0.w, s*c[4*j4+3]));
        }
        if (khalf == h) { c[kk] = -b0; c[kk+1] = -b1; }
    }
    return ld;
}

// prep z-derived tables into caller smem (zsh@0, sal@4096, asz@8448, wrow@12544)
__device__ __forceinline__ void prep_z(char* SMp, const float* __restrict__ z,
                                       const float* __restrict__ alpha, int tid) {
    float* zsh  = (float*)SMp;
    float* sal  = (float*)(SMp + 4096);
    float* asz  = (float*)(SMp + 8448);
    float* wrow = (float*)(SMp + 12544);
    ((float4*)zsh)[tid] = ((const float4*)z)[tid];
    if (tid < Qq) sal[tid] = alpha[tid];
    __syncthreads();
    for (int e = tid; e < Mm*Qq; e += 256) asz[e] = sal[e & 15] * zsh[e];
    __syncthreads();
    if (tid < 64) {
        float w = 0.f;
        #pragma unroll
        for (int q = 0; q < Qq; q++) w = fmaf(asz[tid*Qq + q], zsh[tid*Qq + q], w);
        wrow[tid] = w;
    }
    __syncthreads();
}

// build half-row of k_mm(r, h*32..h*32+31) (+ optional beta*psi2) via Gram expansion
__device__ __forceinline__ void build_row(char* SMp, float c[32], int r, int h,
                                          float var, bool addpsi, float beta) {
    float* zsh  = (float*)SMp;
    float* asz  = (float*)(SMp + 8448);
    float* wrow = (float*)(SMp + 12544);
    const float* ar = &asz[r*Qq];
    float wr = wrow[r];
    const float4* P4 = (const float4*)&g_psi2[r*64 + h*32];
    #pragma unroll
    for (int j4 = 0; j4 < 8; j4++) {
        float4 pv = make_float4(0.f, 0.f, 0.f, 0.f);
        if (addpsi) pv = P4[j4];
        float pl[4] = {pv.x, pv.y, pv.z, pv.w};
        #pragma unroll
        for (int l = 0; l < 4; l++) {
            int col = h*32 + j4*4 + l;
            float dot = 0.f;
            #pragma unroll
            for (int q = 0; q < Qq; q++) dot = fmaf(ar[q], zsh[col*Qq + q], dot);
            float S = wr + wrow[col] - 2.0f*dot;
            float v = var * ex2(-0.5f * LOG2E * S);
            c[4*j4 + l] = addpsi ? fmaf(beta, pl[l], v) : v;
        }
    }
}

__global__ void __launch_bounds__(256, 2) fused(
        const float* __restrict__ y,    const float* __restrict__ qmu,
        const float* __restrict__ qls,  const float* __restrict__ z,
        const float* __restrict__ noise,const float* __restrict__ alpha,
        const float* __restrict__ varp, float* __restrict__ out) {
    __shared__ alignas(16) char SM[32768];
    const int bx = blockIdx.x, tid = threadIdx.x;

    // =========== block 288: mat0 (k_mm) GJ hidden under phase 1 =============
    if (bx == 288) {
        float* SP    = (float*)(SM + 4352);
        float* swarp = (float*)(SM + 12800);
        int r = (tid & 127) >> 1, h = tid & 1, lane = tid & 31;
        prep_z(SM, z, alpha, tid);
        float c[32];
        float ld0 = 0.f;
        if (tid < 128) build_row(SM, c, r, h, varp[0], false, 0.f);
        __syncthreads();
        if (tid < 128) ld0 = gj_run(SP, c, r, h, lane);
        grid_bar();                       // psi2 now complete
        float tr = 0.f;
        if (tid < 128) {
            const float4* T4 = (const float4*)(g_psi2 + r*64 + h*32);
            #pragma unroll
            for (int j4 = 0; j4 < 8; j4++) {
                float4 tv = T4[j4];
                tr = fmaf(c[4*j4+0], tv.x, tr); tr = fmaf(c[4*j4+1], tv.y, tr);
                tr = fmaf(c[4*j4+2], tv.z, tr); tr = fmaf(c[4*j4+3], tv.w, tr);
            }
            #pragma unroll
            for (int sft = 16; sft > 0; sft >>= 1)
                tr += __shfl_xor_sync(0xffffffffu, tr, sft);
            if (lane == 0) swarp[tid >> 5] = tr;
        }
        __syncthreads();
        if (tid == 0) {
            g_res[0] = ld0 * LN2f;
            g_res[1] = swarp[0] + swarp[1] + swarp[2] + swarp[3];
            __threadfence();
            atomicExch(&g_R0done, 1u);
        }
        return;
    }

    // ===================== PHASE 1 =====================
    if (bx < 160) {
        // ---- psi2 unit: pg=bx>>5 → 512 pair-slots; 64 n rows per block ----
        float* zsh  = (float*)SM;              // 1024 f
        float* sal  = (float*)(SM + 4096);     // 16 f
        float* sR2f = (float*)(SM + 4224);     // 64 rows x 144B: u[16],wneg[16],a
        ((float4*)zsh)[tid] = ((const float4*)z)[tid];
        if (tid < Qq) sal[tid] = alpha[tid];
        __syncthreads();
        int pg = bx >> 5, ny = bx & 31;
        int n0 = ny * 64;
        if (tid < 64) {
            int n = n0 + tid;
            float lv2 = lg2(varp[0]);
            float prodD2 = 1.f, P = 0.f;
            float* rw = &sR2f[tid*36];
            #pragma unroll
            for (int q = 0; q < Qq; q++) {
                float mu = qmu[n*Qq + q];
                float x  = qls[n*Qq + q];
                float e  = ex2(-LOG2E * fabsf(x));
                float sg = fmaxf(x, 0.f) + LN2f * lg2(1.0f + e);
                float al = sal[q];
                float d2 = fmaf(2.0f*al, sg, 1.0f);
                prodD2 *= d2;
                float w2 = __fdividef(al, d2);
                P += w2*mu*mu;
                rw[q]      = LOG2E * 2.0f * w2 * mu;
                rw[16 + q] = -LOG2E * w2;
            }
            rw[32] = 4.0f*lv2 - 0.5f*lg2(prodD2) - LOG2E * P;
        }
        int p0 = (pg*256 + tid)*2;
        bool valid = p0 < NPAIR;   // per-thread: p0 and p0+1 valid together
        int iA = 0, jA = 0, iB = 0, jB = 0;
        unsigned long long zpA[8], zpB[8];
        float bA = 0.f, bB = 0.f;
        if (valid) {
            pair_ij(p0,     iA, jA);
            pair_ij(p0 + 1, iB, jB);
            {
                float S = 0.f;
                #pragma unroll
                for (int k = 0; k < 4; k++) {
                    float4 zi = ((const float4*)(zsh + iA*Qq))[k];
                    float4 zj = ((const float4*)(zsh + jA*Qq))[k];
                    zpA[2*k]   = pk2(0.5f*(zi.x+zj.x), 0.5f*(zi.y+zj.y));
                    zpA[2*k+1] = pk2(0.5f*(zi.z+zj.z), 0.5f*(zi.w+zj.w));
                    float dx = zi.x-zj.x, dy = zi.y-zj.y, dz = zi.z-zj.z, dw = zi.w-zj.w;
                    S = fmaf(sal[4*k+0]*dx, dx, S); S = fmaf(sal[4*k+1]*dy, dy, S);
                    S = fmaf(sal[4*k+2]*dz, dz, S); S = fmaf(sal[4*k+3]*dw, dw, S);
                }
                bA = -0.25f * LOG2E * S;
            }
            {
                float S = 0.f;
                #pragma unroll
                for (int k = 0; k < 4; k++) {
                    float4 zi = ((const float4*)(zsh + iB*Qq))[k];
                    float4 zj = ((const float4*)(zsh + jB*Qq))[k];
                    zpB[2*k]   = pk2(0.5f*(zi.x+zj.x), 0.5f*(zi.y+zj.y));
                    zpB[2*k+1] = pk2(0.5f*(zi.z+zj.z), 0.5f*(zi.w+zj.w));
                    float dx = zi.x-zj.x, dy = zi.y-zj.y, dz = zi.z-zj.z, dw = zi.w-zj.w;
                    S = fmaf(sal[4*k+0]*dx, dx, S); S = fmaf(sal[4*k+1]*dy, dy, S);
                    S = fmaf(sal[4*k+2]*dz, dz, S); S = fmaf(sal[4*k+3]*dw, dw, S);
                }
                bB = -0.25f * LOG2E * S;
            }
        }
        __syncthreads();
        if (valid) {
            float sumA = 0.f, sumB = 0.f;
            #pragma unroll 4
            for (int i = 0; i < 64; i++) {
                const char* rowp = (const char*)sR2f + i*144;
                const ulonglong2* up = (const ulonglong2*)rowp;
                const ulonglong2* wp = (const ulonglong2*)(rowp + 64);
                float an = ((const float*)rowp)[32];
                unsigned long long a0 = 0, a1 = 0, b0 = 0, b1 = 0;
                #pragma unroll
                for (int j = 0; j < 4; j++) {
                    ulonglong2 uu = up[j];
                    ulonglong2 ww = wp[j];
                    unsigned long long tA0 = fma2(zpA[2*j],   ww.x, uu.x);
                    unsigned long long tA1 = fma2(zpA[2*j+1], ww.y, uu.y);
                    a0 = fma2(zpA[2*j],   tA0, a0);
                    a1 = fma2(zpA[2*j+1], tA1, a1);
                    unsigned long long tB0 = fma2(zpB[2*j],   ww.x, uu.x);
                    unsigned long long tB1 = fma2(zpB[2*j+1], ww.y, uu.y);
                    b0 = fma2(zpB[2*j],   tB0, b0);
                    b1 = fma2(zpB[2*j+1], tB1, b1);
                }
                float lo, hi;
                upk2(add2(a0, a1), lo, hi);
                sumA += exp2_fast(bA + an + lo + hi);
                upk2(add2(b0, b1), lo, hi);
                sumB += exp2_fast(bB + an + lo + hi);
            }
            atomicAdd(&g_psi2[iA*Mm + jA], sumA);
            if (iA != jA) atomicAdd(&g_psi2[jA*Mm + iA], sumA);
            atomicAdd(&g_psi2[iB*Mm + jB], sumB);
            if (iB != jB) atomicAdd(&g_psi2[jB*Mm + iB], sumB);
        }
    } else {
        // ---- A-GEMM unit: psi1 on the fly + A += psi1^T y + KL; dbl-buf sP ----
        float* zs        = (float*)SM;
        float (*sPP)[36] = (float(*)[36])(SM + 4096);
        float (*sP)[64]  = (float(*)[64])(SM + 22528);   // 2 bufs x 16 x 64
        float* red       = (float*)(SM + 30720);
        int bb = bx - 160;
        int d0 = (bb & 7) * 32;
        int n0 = (bb >> 3) * 128;
        ((float4*)zs)[tid] = ((const float4*)z)[tid];
        float kl = 0.f;
        if (tid < 128) {
            int n = n0 + tid;
            float lv2 = lg2(varp[0]);
            float prodD1 = 1.f, prodSg = 1.f, ss = 0.f;
            #pragma unroll
            for (int q = 0; q < Qq; q++) {
                float mu = qmu[n*Qq + q];
                float x  = qls[n*Qq + q];
                float e  = ex2(-LOG2E * fabsf(x));
                float sg = fmaxf(x, 0.f) + LN2f * lg2(1.0f + e);
                float al = alpha[q];
                ss += fmaf(sg, sg, mu*mu);
                prodSg *= sg;
                float d1 = fmaf(sg, al, 1.0f);
                prodD1 *= d1;
                float w1 = __fdividef(al, d1);
                sPP[tid][q]      = mu;
                sPP[tid][16 + q] = 0.5f * LOG2E * w1;
            }
            sPP[tid][32] = 2.0f*lv2 - 0.5f*lg2(prodD1);
            kl = -LN2f * lg2(prodSg) + 0.5f*(ss - (float)Qq);
        }
        __syncthreads();
        if ((bb & 7) == 0) {
            red[tid] = (tid < 128) ? kl : 0.f;
            __syncthreads();
            #pragma unroll
            for (int s = 128; s > 0; s >>= 1) { if (tid < s) red[tid] += red[tid+s]; __syncthreads(); }
            if (tid == 0) atomicAdd(&g_scal[0], red[0]);
            __syncthreads();
        }
        int jg = tid >> 5, dc = tid & 31;
        unsigned long long acc01 = 0, acc23 = 0, acc45 = 0, acc67 = 0;
        float yy = 0.f;
        for (int s = 0; s < 8; s++) {
            int bo = (s & 1) * 16;
            #pragma unroll
            for (int rr = 0; rr < 4; rr++) {
                int e = tid + 256*rr;
                int nn = e >> 6, j = e & 63;
                const float* U = sPP[s*16 + nn];
                float sacc = U[32];
                #pragma unroll
                for (int q = 0; q < Qq; q++) {
                    float dm = U[q] - zs[j*Qq + q];
                    sacc = fmaf(-U[16+q]*dm, dm, sacc);
                }
                sP[bo + nn][j] = ex2(sacc);
            }
            __syncthreads();
            #pragma unroll
            for (int nn = 0; nn < 16; nn++) {
                float yv = y[(n0 + s*16 + nn)*Dd + d0 + dc];
                if (jg == 0) yy = fmaf(yv, yv, yy);
                unsigned long long yd = pk2(yv, yv);
                const ulonglong2* sp = (const ulonglong2*)&sP[bo + nn][jg*8];
                ulonglong2 pa = sp[0], pb = sp[1];
                acc01 = fma2(yd, pa.x, acc01);
                acc23 = fma2(yd, pa.y, acc23);
                acc45 = fma2(yd, pb.x, acc45);
                acc67 = fma2(yd, pb.y, acc67);
            }
        }
        {
            float v0, v1;
            upk2(acc01, v0, v1);
            atomicAdd(&g_A[(jg*8 + 0)*Dd + d0 + dc], v0);
            atomicAdd(&g_A[(jg*8 + 1)*Dd + d0 + dc], v1);
            upk2(acc23, v0, v1);
            atomicAdd(&g_A[(jg*8 + 2)*Dd + d0 + dc], v0);
            atomicAdd(&g_A[(jg*8 + 3)*Dd + d0 + dc], v1);
            upk2(acc45, v0, v1);
            atomicAdd(&g_A[(jg*8 + 4)*Dd + d0 + dc], v0);
            atomicAdd(&g_A[(jg*8 + 5)*Dd + d0 + dc], v1);
            upk2(acc67, v0, v1);
            atomicAdd(&g_A[(jg*8 + 6)*Dd + d0 + dc], v0);
            atomicAdd(&g_A[(jg*8 + 7)*Dd + d0 + dc], v1);
        }
        __syncthreads();
        red[tid] = yy; __syncthreads();
        #pragma unroll
        for (int s = 128; s > 0; s >>= 1) { if (tid < s) red[tid] += red[tid+s]; __syncthreads(); }
        if (tid == 0) atomicAdd(&g_scal[1], red[0]);
    }

    grid_bar();

    // ===================== PHASE 2: G = A A^T (blocks 0..31) =================
    if (bx < 32) {
        float* a0s     = (float*)SM;
        float* a1s     = (float*)(SM + 1024);
        float (*sG)[8] = (float(*)[8])(SM + 2048);
        int r0 = bx * 2, r1 = r0 + 1;
        a0s[tid] = g_A[r0*Dd + tid];
        a1s[tid] = g_A[r1*Dd + tid];
        __syncthreads();
        int k = tid >> 2, q = tid & 3;
        const float4* bv4  = (const float4*)&g_A[k*Dd + q*64];
        const float4* av04 = (const float4*)&a0s[q*64];
        const float4* av14 = (const float4*)&a1s[q*64];
        float s0 = 0.f, s1 = 0.f;
        #pragma unroll
        for (int d = 0; d < 16; d++) {
            float4 b = bv4[d], a0 = av04[d], a1 = av14[d];
            s0 = fmaf(a0.x,b.x,s0); s0 = fmaf(a0.y,b.y,s0); s0 = fmaf(a0.z,b.z,s0); s0 = fmaf(a0.w,b.w,s0);
            s1 = fmaf(a1.x,b.x,s1); s1 = fmaf(a1.y,b.y,s1); s1 = fmaf(a1.z,b.z,s1); s1 = fmaf(a1.w,b.w,s1);
        }
        sG[k][q] = s0; sG[k][4 + q] = s1;
        __syncthreads();
        if (tid < 64)
            g_G[r0*Mm + tid] = sG[tid][0] + sG[tid][1] + sG[tid][2] + sG[tid][3];
        else if (tid < 128) {
            int t = tid - 64;
            g_G[r1*Mm + t] = sG[t][4] + sG[t][5] + sG[t][6] + sG[t][7];
        }
        __threadfence();
        __syncthreads();
        if (tid == 0) atomicAdd(&g_Gdone, 1u);
        return;
    }
    if (bx != 32) return;

    // ===== PHASE 3 (block 32): cov1-only GJ + traces + final + zero tail =====
    {
        float* SP    = (float*)(SM + 4352);
        float* swarp = (float*)(SM + 12800);
        float* sres  = (float*)(SM + 12864);
        int r = (tid & 127) >> 1, h = tid & 1, lane = tid & 31;
        float beta = 1.0f / softplus_f(noise[0]);
        float var  = varp[0];

        prep_z(SM, z, alpha, tid);
        float c[32];
        float ld1 = 0.f;
        if (tid < 128) build_row(SM, c, r, h, var, true, beta);
        __syncthreads();
        if (tid < 128) ld1 = gj_run(SP, c, r, h, lane);

        // wait for G blocks and block 288's mat0 results
        if (tid == 0) {
            while (atomicAdd(&g_Gdone, 0u) < 32u || atomicAdd(&g_R0done, 0u) == 0u)
                __nanosleep(64);
        }
        __syncthreads();
        __threadfence();

        float tr = 0.f;
        if (tid < 128) {
            const float4* T4 = (const float4*)(g_G + r*64 + h*32);
            #pragma unroll
            for (int j4 = 0; j4 < 8; j4++) {
                float4 tv = T4[j4];
                tr = fmaf(c[4*j4+0], tv.x, tr); tr = fmaf(c[4*j4+1], tv.y, tr);
                tr = fmaf(c[4*j4+2], tv.z, tr); tr = fmaf(c[4*j4+3], tv.w, tr);
            }
            #pragma unroll
            for (int sft = 16; sft > 0; sft >>= 1)
                tr += __shfl_xor_sync(0xffffffffu, tr, sft);
            if (lane == 0) swarp[tid >> 5] = tr;
            if (tid == 0) sres[0] = ld1 * LN2f;
        }
        // snapshot scalars BEFORE the zeroing pass
        float klsum = g_scal[0];
        float yysum = g_scal[1];
        float ld0   = g_res[0];
        float tr0   = g_res[1];
        __syncthreads();

        // ---- zero accumulators for next graph replay ----
        float4 z4 = make_float4(0.f, 0.f, 0.f, 0.f);
        for (int i = tid; i < 4096; i += 256) ((float4*)g_A)[i] = z4;
        for (int i = tid; i < 1024; i += 256) ((float4*)g_psi2)[i] = z4;
        if (tid < 8) g_scal[tid] = 0.f;
        if (tid == 9)  g_Gdone = 0u;
        if (tid == 10) g_R0done = 0u;

        if (tid == 0) {
            float tr1 = swarp[0] + swarp[1] + swarp[2] + swarp[3];
            double kl = (double)klsum / ((double)Nn * (double)Dd);
            double nd = (double)Nn * (double)Dd;
            double F = 0.5 * Nn * log((double)beta)
                     + 0.5 * (double)ld0
                     - 0.5 * Nn * log(3.14159265358979323846)
                     - 0.5 * (double)sres[0]
                     - 0.5 * (double)beta * ((double)Nn * (double)var)
                     + 0.5 * (double)tr0;
            double tr_yWy = (double)beta * (double)yysum - (double)tr1;
            F = (F * Dd - 0.5 * tr_yWy) / nd;
            out[0] = (float)(F - kl);
        }
    }
}

extern "C" void kernel_launch(void* const* d_in, const int* in_sizes, int n_in,
                              void* d_out, int out_size) {
    const float* y     = (const float*)d_in[0];
    const float* qmu   = (const float*)d_in[1];
    const float* qls   = (const float*)d_in[2];
    const float* z     = (const float*)d_in[3];
    const float* noise = (const float*)d_in[4];
    const float* alpha = (const float*)d_in[5];
    const float* varp  = (const float*)d_in[6];
    float* out = (float*)d_out;

    fused<<<NBLK, 256>>>(y, qmu, qls, z, noise, alpha, varp, out);
}

// round 15
// speedup vs baseline: 1.3903x; 1.2394x over previous
#include <cuda_runtime.h>
#include <math.h>

#define Nn 2048
#define Dd 256
#define Qq 16
#define Mm 64
#define MMs 4096
#define NPAIR 2080
#define NBLK 290
#define BARN 289
#define LOG2E 1.4426950408889634f
#define LN2f  0.6931471805599453f

// -------- scratch (device globals; zero at load, re-zeroed by tail) -----
__device__ alignas(16) float g_psi2[MMs];
__device__ alignas(16) float g_A[Mm*Dd];
__device__ alignas(16) float g_G[MMs];
__device__ float  g_scal[8];          // [0]=KL sum, [1]=sum(y*y)
__device__ float  g_res[4];           // [0]=ld0, [1]=tr0 (from block 288)
__device__ unsigned g_Gdone;
__device__ unsigned g_R0done;
__device__ unsigned g_P2done;
__device__ unsigned g_cnt;
__device__ volatile unsigned g_gen;

__device__ __forceinline__ float softplus_f(float x) {
    float ax = fabsf(x);
    return fmaxf(x, 0.0f) + log1pf(__expf(-ax));
}
__device__ __forceinline__ float ex2(float x) {
    float y; asm("ex2.approx.f32 %0, %1;" : "=f"(y) : "f"(x)); return y;
}
__device__ __forceinline__ float lg2(float x) {
    float y; asm("lg2.approx.f32 %0, %1;" : "=f"(y) : "f"(x)); return y;
}
// FMA-pipe exp2 (psi2 hot loop; avoids MUFU wall). |rel err| ~2.4e-6
__device__ __forceinline__ float exp2_fast(float x) {
    x = fmaxf(x, -125.0f);
    float r = rintf(x);
    float f = x - r;
    int   i = (int)r;
    float p =          1.3333558146e-3f;
    p = fmaf(p, f,     9.6181291076e-3f);
    p = fmaf(p, f,     5.5504108664e-2f);
    p = fmaf(p, f,     2.4022650696e-1f);
    p = fmaf(p, f,     6.9314718056e-1f);
    p = fmaf(p, f,     1.0f);
    return __int_as_float(__float_as_int(p) + (i << 23));
}

// ---- packed f32x2 helpers ----
__device__ __forceinline__ unsigned long long pk2(float lo, float hi) {
    unsigned long long r;
    asm("mov.b64 %0, {%1, %2};" : "=l"(r) : "f"(lo), "f"(hi));
    return r;
}
__device__ __forceinline__ void upk2(unsigned long long v, float& lo, float& hi) {
    asm("mov.b64 {%0, %1}, %2;" : "=f"(lo), "=f"(hi) : "l"(v));
}
__device__ __forceinline__ unsigned long long fma2(unsigned long long a,
                                                   unsigned long long b,
                                                   unsigned long long c) {
    unsigned long long d;
    asm("fma.rn.f32x2 %0, %1, %2, %3;" : "=l"(d) : "l"(a), "l"(b), "l"(c));
    return d;
}
__device__ __forceinline__ unsigned long long add2(unsigned long long a,
                                                   unsigned long long b) {
    unsigned long long d;
    asm("add.rn.f32x2 %0, %1, %2;" : "=l"(d) : "l"(a), "l"(b));
    return d;
}

__device__ __forceinline__ int tri_base(int i) { return i*Mm - ((i*(i-1)) >> 1); }
__device__ __forceinline__ void pair_ij(int p, int& io, int& jo) {
    int ii = (int)(0.5f*(129.0f - sqrtf(fmaf(-8.f, (float)p, 16641.f))));
    while (tri_base(ii+1) <= p) ii++;
    while (tri_base(ii)   >  p) ii--;
    io = ii;
    jo = p - tri_base(ii) + ii;
}

// grid-wide barrier (blocks 0..288 only; block 289 never calls)
__device__ __forceinline__ void grid_bar() {
    __threadfence();
    __syncthreads();
    if (threadIdx.x == 0) {
        unsigned gen = g_gen;
        if (atomicAdd(&g_cnt, 1u) == BARN - 1u) {
            g_cnt = 0u;
            __threadfence();
            g_gen = gen + 1u;
        } else {
            while (g_gen == gen) __nanosleep(32);
        }
    }
    __syncthreads();
    __threadfence();
}

// half-row Gauss-Jordan on a 64x64 SPD matrix distributed as 128 threads x
// 32-col half-rows. SP = caller's 256-float pivot region (2 bufs x 2 rows x 64).
__device__ __forceinline__ float gj_run(float* SP, float c[32],
                                        int r, int h, int lane) {
    float ld = 0.f;
    #pragma unroll
    for (int k = 0; k < 64; k += 2) {
        const int buf = (k >> 1) & 1;
        const int khalf = k >> 5;
        const int kk = k & 31;
        if (r == k || r == k + 1) {
            float4* s4 = (float4*)&SP[(buf*2 + (r - k))*64 + h*32];
            #pragma unroll
            for (int j4 = 0; j4 < 8; j4++)
                s4[j4] = make_float4(c[4*j4], c[4*j4+1], c[4*j4+2], c[4*j4+3]);
        }
        asm volatile("bar.sync 1, 128;" ::: "memory");
        const float* R0 = &SP[(buf*2 + 0)*64];
        const float* R1 = &SP[(buf*2 + 1)*64];
        float R0k = R0[k], R0k1 = R0[k+1];
        float R1k = R1[k], R1k1 = R1[k+1];
        float rp0; asm("rcp.approx.f32 %0, %1;" : "=f"(rp0) : "f"(R0k));
        rp0 = rp0 * (2.0f - R0k * rp0);
        float g = R1k * rp0;
        float p1 = fmaf(-g, R0k1, R1k1);
        float rp1; asm("rcp.approx.f32 %0, %1;" : "=f"(rp1) : "f"(p1));
        rp1 = rp1 * (2.0f - p1 * rp1);
        ld += lg2(R0k) + lg2(p1);
        int src = (lane & ~1) | khalf;
        float f0 = __shfl_sync(0xffffffffu, c[kk],   src);
        float m1 = __shfl_sync(0xffffffffu, c[kk+1], src);
        float b0, b1, s;
        if (r == k) {
            float fr1k = rp0 * R0k1 * rp1;
            b0 = -fmaf(fr1k, g, rp0);  b1 = fr1k;   s = 0.f;
        } else if (r == k + 1) {
            b0 = rp1 * g;              b1 = -rp1;   s = 0.f;
        } else {
            float fr0 = f0 * rp0;
            float f1 = fmaf(-fr0, R0k1, m1);
            float fr1 = f1 * rp1;
            b0 = fmaf(-fr1, g, fr0);   b1 = fr1;    s = 1.f;
        }
        const float4* P04 = (const float4*)&R0[h*32];
        const float4* P14 = (const float4*)&R1[h*32];
        #pragma unroll
        for (int j4 = 0; j4 < 8; j4++) {
            float4 q0 = P04[j4], q1 = P14[j4];
            c[4*j4+0] = fmaf(-b1, q1.x, fmaf(-b0, q0.x, s*c[4*j4+0]));
            c[4*j4+1] = fmaf(-b1, q1.y, fmaf(-b0, q0.y, s*c[4*j4+1]));
            c[4*j4+2] = fmaf(-b1, q1.z, fmaf(-b0, q0.z, s*c[4*j4+2]));
            c[4*j4+3] = fmaf(-b1, q1.w, fmaf(-b0, q0.w, s*c[4*j4+3]));
        }
        if (khalf == h) { c[kk] = -b0; c[kk+1] = -b1; }
    }
    return ld;
}

// prep z-derived tables into caller smem (zsh@0, sal@4096, asz@8448, wrow@12544)
__device__ __forceinline__ void prep_z(char* SMp, const float* __restrict__ z,
                                       const float* __restrict__ alpha, int tid) {
    float* zsh  = (float*)SMp;
    float* sal  = (float*)(SMp + 4096);
    float* asz  = (float*)(SMp + 8448);
    float* wrow = (float*)(SMp + 12544);
    ((float4*)zsh)[tid] = ((const float4*)z)[tid];
    if (tid < Qq) sal[tid] = alpha[tid];
    __syncthreads();
    for (int e = tid; e < Mm*Qq; e += 256) asz[e] = sal[e & 15] * zsh[e];
    __syncthreads();
    if (tid < 64) {
        float w = 0.f;
        #pragma unroll
        for (int q = 0; q < Qq; q++) w = fmaf(asz[tid*Qq + q], zsh[tid*Qq + q], w);
        wrow[tid] = w;
    }
    __syncthreads();
}

// build half-row of k_mm(r, h*32..h*32+31) via Gram expansion (no psi2 term)
__device__ __forceinline__ void build_row(char* SMp, float c[32], int r, int h,
                                          float var) {
    float* zsh  = (float*)SMp;
    float* asz  = (float*)(SMp + 8448);
    float* wrow = (float*)(SMp + 12544);
    const float* ar = &asz[r*Qq];
    float wr = wrow[r];
    #pragma unroll
    for (int j4 = 0; j4 < 8; j4++) {
        #pragma unroll
        for (int l = 0; l < 4; l++) {
            int col = h*32 + j4*4 + l;
            float dot = 0.f;
            #pragma unroll
            for (int q = 0; q < Qq; q++) dot = fmaf(ar[q], zsh[col*Qq + q], dot);
            float S = wr + wrow[col] - 2.0f*dot;
            c[4*j4 + l] = var * ex2(-0.5f * LOG2E * S);
        }
    }
}

__global__ void __launch_bounds__(256, 2) fused(
        const float* __restrict__ y,    const float* __restrict__ qmu,
        const float* __restrict__ qls,  const float* __restrict__ z,
        const float* __restrict__ noise,const float* __restrict__ alpha,
        const float* __restrict__ varp, float* __restrict__ out) {
    __shared__ alignas(16) char SM[32768];
    const int bx = blockIdx.x, tid = threadIdx.x;

    // ====== block 289: cov1 GJ decoupled from the bar (waits on psi2 only) ===
    if (bx == 289) {
        float* SP    = (float*)(SM + 4352);
        float* swarp = (float*)(SM + 12800);
        int r = (tid & 127) >> 1, h = tid & 1, lane = tid & 31;
        float beta = 1.0f / softplus_f(noise[0]);
        float var  = varp[0];
        prep_z(SM, z, alpha, tid);
        float c[32];
        if (tid < 128) build_row(SM, c, r, h, var);   // k_mm part, psi2-independent
        // wait for all psi2 blocks
        if (tid == 0) { while (atomicAdd(&g_P2done, 0u) < 160u) __nanosleep(32); }
        __syncthreads();
        __threadfence();
        float ld1 = 0.f;
        if (tid < 128) {
            const float4* P4 = (const float4*)&g_psi2[r*64 + h*32];
            #pragma unroll
            for (int j4 = 0; j4 < 8; j4++) {
                float4 pv = P4[j4];
                c[4*j4+0] = fmaf(beta, pv.x, c[4*j4+0]);
                c[4*j4+1] = fmaf(beta, pv.y, c[4*j4+1]);
                c[4*j4+2] = fmaf(beta, pv.z, c[4*j4+2]);
                c[4*j4+3] = fmaf(beta, pv.w, c[4*j4+3]);
            }
            ld1 = gj_run(SP, c, r, h, lane);
        }
        // wait for G blocks and block 288's mat0 results (implies all scal final)
        if (tid == 0) {
            while (atomicAdd(&g_Gdone, 0u) < 32u || atomicAdd(&g_R0done, 0u) == 0u)
                __nanosleep(64);
        }
        __syncthreads();
        __threadfence();
        float tr = 0.f;
        if (tid < 128) {
            const float4* T4 = (const float4*)(g_G + r*64 + h*32);
            #pragma unroll
            for (int j4 = 0; j4 < 8; j4++) {
                float4 tv = T4[j4];
                tr = fmaf(c[4*j4+0], tv.x, tr); tr = fmaf(c[4*j4+1], tv.y, tr);
                tr = fmaf(c[4*j4+2], tv.z, tr); tr = fmaf(c[4*j4+3], tv.w, tr);
            }
            #pragma unroll
            for (int sft = 16; sft > 0; sft >>= 1)
                tr += __shfl_xor_sync(0xffffffffu, tr, sft);
            if (lane == 0) swarp[tid >> 5] = tr;
        }
        // snapshot scalars BEFORE the zeroing pass
        float klsum = g_scal[0];
        float yysum = g_scal[1];
        float ld0   = g_res[0];
        float tr0   = g_res[1];
        __syncthreads();
        // ---- zero accumulators for next graph replay ----
        float4 z4 = make_float4(0.f, 0.f, 0.f, 0.f);
        for (int i = tid; i < 4096; i += 256) ((float4*)g_A)[i] = z4;
        for (int i = tid; i < 1024; i += 256) ((float4*)g_psi2)[i] = z4;
        if (tid < 8) g_scal[tid] = 0.f;
        if (tid == 9)  g_Gdone = 0u;
        if (tid == 10) g_R0done = 0u;
        if (tid == 11) g_P2done = 0u;
        if (tid == 0) {
            float tr1 = swarp[0] + swarp[1] + swarp[2] + swarp[3];
            double kl = (double)klsum / ((double)Nn * (double)Dd);
            double nd = (double)Nn * (double)Dd;
            double F = 0.5 * Nn * log((double)beta)
                     + 0.5 * (double)ld0
                     - 0.5 * Nn * log(3.14159265358979323846)
                     - 0.5 * (double)(ld1 * LN2f)
                     - 0.5 * (double)beta * ((double)Nn * (double)var)
                     + 0.5 * (double)tr0;
            double tr_yWy = (double)beta * (double)yysum - (double)tr1;
            F = (F * Dd - 0.5 * tr_yWy) / nd;
            out[0] = (float)(F - kl);
        }
        return;
    }

    // =========== block 288: mat0 (k_mm) GJ hidden under phase 1 =============
    if (bx == 288) {
        float* SP    = (float*)(SM + 4352);
        float* swarp = (float*)(SM + 12800);
        int r = (tid & 127) >> 1, h = tid & 1, lane = tid & 31;
        prep_z(SM, z, alpha, tid);
        float c[32];
        float ld0 = 0.f;
        if (tid < 128) build_row(SM, c, r, h, varp[0]);
        __syncthreads();
        if (tid < 128) ld0 = gj_run(SP, c, r, h, lane);
        grid_bar();                       // psi2 now complete
        float tr = 0.f;
        if (tid < 128) {
            const float4* T4 = (const float4*)(g_psi2 + r*64 + h*32);
            #pragma unroll
            for (int j4 = 0; j4 < 8; j4++) {
                float4 tv = T4[j4];
                tr = fmaf(c[4*j4+0], tv.x, tr); tr = fmaf(c[4*j4+1], tv.y, tr);
                tr = fmaf(c[4*j4+2], tv.z, tr); tr = fmaf(c[4*j4+3], tv.w, tr);
            }
            #pragma unroll
            for (int sft = 16; sft > 0; sft >>= 1)
                tr += __shfl_xor_sync(0xffffffffu, tr, sft);
            if (lane == 0) swarp[tid >> 5] = tr;
        }
        __syncthreads();
        if (tid == 0) {
            g_res[0] = ld0 * LN2f;
            g_res[1] = swarp[0] + swarp[1] + swarp[2] + swarp[3];
            __threadfence();
            atomicExch(&g_R0done, 1u);
        }
        return;
    }

    // ===================== PHASE 1 =====================
    if (bx < 160) {
        // ---- psi2 unit: pg=bx>>5 → 512 pair-slots; 64 n rows per block ----
        float* zsh  = (float*)SM;              // 1024 f
        float* sal  = (float*)(SM + 4096);     // 16 f
        float* sR2f = (float*)(SM + 4224);     // 64 rows x 144B: u[16],wneg[16],a
        ((float4*)zsh)[tid] = ((const float4*)z)[tid];
        if (tid < Qq) sal[tid] = alpha[tid];
        __syncthreads();
        int pg = bx >> 5, ny = bx & 31;
        int n0 = ny * 64;
        if (tid < 64) {
            int n = n0 + tid;
            float lv2 = lg2(varp[0]);
            float prodD2 = 1.f, P = 0.f;
            float* rw = &sR2f[tid*36];
            #pragma unroll
            for (int q = 0; q < Qq; q++) {
                float mu = qmu[n*Qq + q];
                float x  = qls[n*Qq + q];
                float e  = ex2(-LOG2E * fabsf(x));
                float sg = fmaxf(x, 0.f) + LN2f * lg2(1.0f + e);
                float al = sal[q];
                float d2 = fmaf(2.0f*al, sg, 1.0f);
                prodD2 *= d2;
                float w2 = __fdividef(al, d2);
                P += w2*mu*mu;
                rw[q]      = LOG2E * 2.0f * w2 * mu;
                rw[16 + q] = -LOG2E * w2;
            }
            rw[32] = 4.0f*lv2 - 0.5f*lg2(prodD2) - LOG2E * P;
        }
        int p0 = (pg*256 + tid)*2;
        bool valid = p0 < NPAIR;
        int iA = 0, jA = 0, iB = 0, jB = 0;
        unsigned long long zpA[8], zpB[8];
        float bA = 0.f, bB = 0.f;
        if (valid) {
            pair_ij(p0,     iA, jA);
            pair_ij(p0 + 1, iB, jB);
            {
                float S = 0.f;
                #pragma unroll
                for (int k = 0; k < 4; k++) {
                    float4 zi = ((const float4*)(zsh + iA*Qq))[k];
                    float4 zj = ((const float4*)(zsh + jA*Qq))[k];
                    zpA[2*k]   = pk2(0.5f*(zi.x+zj.x), 0.5f*(zi.y+zj.y));
                    zpA[2*k+1] = pk2(0.5f*(zi.z+zj.z), 0.5f*(zi.w+zj.w));
                    float dx = zi.x-zj.x, dy = zi.y-zj.y, dz = zi.z-zj.z, dw = zi.w-zj.w;
                    S = fmaf(sal[4*k+0]*dx, dx, S); S = fmaf(sal[4*k+1]*dy, dy, S);
                    S = fmaf(sal[4*k+2]*dz, dz, S); S = fmaf(sal[4*k+3]*dw, dw, S);
                }
                bA = -0.25f * LOG2E * S;
            }
            {
                float S = 0.f;
                #pragma unroll
                for (int k = 0; k < 4; k++) {
                    float4 zi = ((const float4*)(zsh + iB*Qq))[k];
                    float4 zj = ((const float4*)(zsh + jB*Qq))[k];
                    zpB[2*k]   = pk2(0.5f*(zi.x+zj.x), 0.5f*(zi.y+zj.y));
                    zpB[2*k+1] = pk2(0.5f*(zi.z+zj.z), 0.5f*(zi.w+zj.w));
                    float dx = zi.x-zj.x, dy = zi.y-zj.y, dz = zi.z-zj.z, dw = zi.w-zj.w;
                    S = fmaf(sal[4*k+0]*dx, dx, S); S = fmaf(sal[4*k+1]*dy, dy, S);
                    S = fmaf(sal[4*k+2]*dz, dz, S); S = fmaf(sal[4*k+3]*dw, dw, S);
                }
                bB = -0.25f * LOG2E * S;
            }
        }
        __syncthreads();
        if (valid) {
            float sumA = 0.f, sumB = 0.f;
            #pragma unroll 4
            for (int i = 0; i < 64; i++) {
                const char* rowp = (const char*)sR2f + i*144;
                const ulonglong2* up = (const ulonglong2*)rowp;
                const ulonglong2* wp = (const ulonglong2*)(rowp + 64);
                float an = ((const float*)rowp)[32];
                unsigned long long a0 = 0, a1 = 0, b0 = 0, b1 = 0;
                #pragma unroll
                for (int j = 0; j < 4; j++) {
                    ulonglong2 uu = up[j];
                    ulonglong2 ww = wp[j];
                    unsigned long long tA0 = fma2(zpA[2*j],   ww.x, uu.x);
                    unsigned long long tA1 = fma2(zpA[2*j+1], ww.y, uu.y);
                    a0 = fma2(zpA[2*j],   tA0, a0);
                    a1 = fma2(zpA[2*j+1], tA1, a1);
                    unsigned long long tB0 = fma2(zpB[2*j],   ww.x, uu.x);
                    unsigned long long tB1 = fma2(zpB[2*j+1], ww.y, uu.y);
                    b0 = fma2(zpB[2*j],   tB0, b0);
                    b1 = fma2(zpB[2*j+1], tB1, b1);
                }
                float lo, hi;
                upk2(add2(a0, a1), lo, hi);
                sumA += exp2_fast(bA + an + lo + hi);
                upk2(add2(b0, b1), lo, hi);
                sumB += exp2_fast(bB + an + lo + hi);
            }
            atomicAdd(&g_psi2[iA*Mm + jA], sumA);
            if (iA != jA) atomicAdd(&g_psi2[jA*Mm + iA], sumA);
            atomicAdd(&g_psi2[iB*Mm + jB], sumB);
            if (iB != jB) atomicAdd(&g_psi2[jB*Mm + iB], sumB);
        }
        // signal psi2 completion for block 289
        __threadfence();
        __syncthreads();
        if (tid == 0) atomicAdd(&g_P2done, 1u);
    } else {
        // ---- A-GEMM unit: psi1 on the fly + A += psi1^T y + KL; dbl-buf sP ----
        float* zs        = (float*)SM;
        float (*sPP)[36] = (float(*)[36])(SM + 4096);
        float (*sP)[64]  = (float(*)[64])(SM + 22528);   // 2 bufs x 16 x 64
        float* red       = (float*)(SM + 30720);
        int bb = bx - 160;
        int d0 = (bb & 7) * 32;
        int n0 = (bb >> 3) * 128;
        ((float4*)zs)[tid] = ((const float4*)z)[tid];
        float kl = 0.f;
        if (tid < 128) {
            int n = n0 + tid;
            float lv2 = lg2(varp[0]);
            float prodD1 = 1.f, prodSg = 1.f, ss = 0.f;
            #pragma unroll
            for (int q = 0; q < Qq; q++) {
                float mu = qmu[n*Qq + q];
                float x  = qls[n*Qq + q];
                float e  = ex2(-LOG2E * fabsf(x));
                float sg = fmaxf(x, 0.f) + LN2f * lg2(1.0f + e);
                float al = alpha[q];
                ss += fmaf(sg, sg, mu*mu);
                prodSg *= sg;
                float d1 = fmaf(sg, al, 1.0f);
                prodD1 *= d1;
                float w1 = __fdividef(al, d1);
                sPP[tid][q]      = mu;
                sPP[tid][16 + q] = 0.5f * LOG2E * w1;
            }
            sPP[tid][32] = 2.0f*lv2 - 0.5f*lg2(prodD1);
            kl = -LN2f * lg2(prodSg) + 0.5f*(ss - (float)Qq);
        }
        __syncthreads();
        if ((bb & 7) == 0) {
            red[tid] = (tid < 128) ? kl : 0.f;
            __syncthreads();
            #pragma unroll
            for (int s = 128; s > 0; s >>= 1) { if (tid < s) red[tid] += red[tid+s]; __syncthreads(); }
            if (tid == 0) atomicAdd(&g_scal[0], red[0]);
            __syncthreads();
        }
        int jg = tid >> 5, dc = tid & 31;
        unsigned long long acc01 = 0, acc23 = 0, acc45 = 0, acc67 = 0;
        float yy = 0.f;
        for (int s = 0; s < 8; s++) {
            int bo = (s & 1) * 16;
            #pragma unroll
            for (int rr = 0; rr < 4; rr++) {
                int e = tid + 256*rr;
                int nn = e >> 6, j = e & 63;
                const float* U = sPP[s*16 + nn];
                float sacc = U[32];
                #pragma unroll
                for (int q = 0; q < Qq; q++) {
                    float dm = U[q] - zs[j*Qq + q];
                    sacc = fmaf(-U[16+q]*dm, dm, sacc);
                }
                sP[bo + nn][j] = ex2(sacc);
            }
            __syncthreads();
            #pragma unroll
            for (int nn = 0; nn < 16; nn++) {
                float yv = y[(n0 + s*16 + nn)*Dd + d0 + dc];
                if (jg == 0) yy = fmaf(yv, yv, yy);
                unsigned long long yd = pk2(yv, yv);
                const ulonglong2* sp = (const ulonglong2*)&sP[bo + nn][jg*8];
                ulonglong2 pa = sp[0], pb = sp[1];
                acc01 = fma2(yd, pa.x, acc01);
                acc23 = fma2(yd, pa.y, acc23);
                acc45 = fma2(yd, pb.x, acc45);
                acc67 = fma2(yd, pb.y, acc67);
            }
        }
        {
            float v0, v1;
            upk2(acc01, v0, v1);
            atomicAdd(&g_A[(jg*8 + 0)*Dd + d0 + dc], v0);
            atomicAdd(&g_A[(jg*8 + 1)*Dd + d0 + dc], v1);
            upk2(acc23, v0, v1);
            atomicAdd(&g_A[(jg*8 + 2)*Dd + d0 + dc], v0);
            atomicAdd(&g_A[(jg*8 + 3)*Dd + d0 + dc], v1);
            upk2(acc45, v0, v1);
            atomicAdd(&g_A[(jg*8 + 4)*Dd + d0 + dc], v0);
            atomicAdd(&g_A[(jg*8 + 5)*Dd + d0 + dc], v1);
            upk2(acc67, v0, v1);
            atomicAdd(&g_A[(jg*8 + 6)*Dd + d0 + dc], v0);
            atomicAdd(&g_A[(jg*8 + 7)*Dd + d0 + dc], v1);
        }
        __syncthreads();
        red[tid] = yy; __syncthreads();
        #pragma unroll
        for (int s = 128; s > 0; s >>= 1) { if (tid < s) red[tid] += red[tid+s]; __syncthreads(); }
        if (tid == 0) atomicAdd(&g_scal[1], red[0]);
    }

    grid_bar();

    // ===================== PHASE 2: G = A A^T (blocks 0..31) =================
    if (bx < 32) {
        float* a0s     = (float*)SM;
        float* a1s     = (float*)(SM + 1024);
        float (*sG)[8] = (float(*)[8])(SM + 2048);
        int r0 = bx * 2, r1 = r0 + 1;
        a0s[tid] = g_A[r0*Dd + tid];
        a1s[tid] = g_A[r1*Dd + tid];
        __syncthreads();
        int k = tid >> 2, q = tid & 3;
        const float4* bv4  = (const float4*)&g_A[k*Dd + q*64];
        const float4* av04 = (const float4*)&a0s[q*64];
        const float4* av14 = (const float4*)&a1s[q*64];
        float s0 = 0.f, s1 = 0.f;
        #pragma unroll
        for (int d = 0; d < 16; d++) {
            float4 b = bv4[d], a0 = av04[d], a1 = av14[d];
            s0 = fmaf(a0.x,b.x,s0); s0 = fmaf(a0.y,b.y,s0); s0 = fmaf(a0.z,b.z,s0); s0 = fmaf(a0.w,b.w,s0);
            s1 = fmaf(a1.x,b.x,s1); s1 = fmaf(a1.y,b.y,s1); s1 = fmaf(a1.z,b.z,s1); s1 = fmaf(a1.w,b.w,s1);
        }
        sG[k][q] = s0; sG[k][4 + q] = s1;
        __syncthreads();
        if (tid < 64)
            g_G[r0*Mm + tid] = sG[tid][0] + sG[tid][1] + sG[tid][2] + sG[tid][3];
        else if (tid < 128) {
            int t = tid - 64;
            g_G[r1*Mm + t] = sG[t][4] + sG[t][5] + sG[t][6] + sG[t][7];
        }
        __threadfence();
        __syncthreads();
        if (tid == 0) atomicAdd(&g_Gdone, 1u);
    }
    // all phase-1 blocks exit; block 289 finishes the reduction
}

extern "C" void kernel_launch(void* const* d_in, const int* in_sizes, int n_in,
                              void* d_out, int out_size) {
    const float* y     = (const float*)d_in[0];
    const float* qmu   = (const float*)d_in[1];
    const float* qls   = (const float*)d_in[2];
    const float* z     = (const float*)d_in[3];
    const float* noise = (const float*)d_in[4];
    const float* alpha = (const float*)d_in[5];
    const float* varp  = (const float*)d_in[6];
    float* out = (float*)d_out;

    fused<<<NBLK, 256>>>(y, qmu, qls, z, noise, alpha, varp, out);
}